// round 1
// baseline (speedup 1.0000x reference)
#include <cuda_runtime.h>
#include <math.h>
#include <stdint.h>

// ---------------- problem constants ----------------
#define S_LEN 1024
#define HID_D 7168
#define NH 128
#define DN 128      // D_NOPE
#define DR 64       // D_ROPE
#define DV 128      // D_V
#define QLORA 1536
#define KVLORA 512
#define COMP_D (QLORA + KVLORA + DR)      // 2112
#define QD (NH * (DN + DR))               // 24576
#define KVD (NH * (DN + DV))              // 32768
#define CTX_D (NH * DV)                   // 16384

// ---------------- scratch (device globals; no runtime allocation) ----------------
__device__ float g_comp[S_LEN * COMP_D];                     // 8.7 MB
__device__ float g_qn[S_LEN * QLORA];                        // 6.3 MB
__device__ float g_kvn[S_LEN * KVLORA];                      // 2.1 MB
__device__ float g_q[(size_t)S_LEN * QD];                    // 100 MB
__device__ float g_kv[(size_t)S_LEN * KVD];                  // 134 MB
__device__ float g_kpe[S_LEN * DR];                          // 256 KB
__device__ float g_attn[(size_t)NH * S_LEN * S_LEN];         // 537 MB
__device__ float g_ctx[(size_t)S_LEN * CTX_D];               // 67 MB

// ---------------- generic tiled SGEMM: C[M,N] = A[M,K] @ B[K,N] ----------------
// BM=BN=128, BK=8, 256 threads, 8x8 per thread. M%128==0 and K%8==0 assumed
// (true for all call sites); N guarded (handles N=2112).
__global__ __launch_bounds__(256) void sgemm128(
    const float* __restrict__ A, const float* __restrict__ B,
    float* __restrict__ C, int M, int N, int K)
{
    __shared__ float As[8][128];
    __shared__ float Bs[8][128];

    const int tid  = threadIdx.x;
    const int brow = blockIdx.y;
    const int bcol = blockIdx.x;
    const int ty = tid >> 4;        // 0..15
    const int tx = tid & 15;        // 0..15

    float acc[8][8];
#pragma unroll
    for (int i = 0; i < 8; i++)
#pragma unroll
        for (int j = 0; j < 8; j++) acc[i][j] = 0.0f;

    const int aRow = tid >> 1;           // 0..127
    const int aCol = (tid & 1) * 4;      // 0 or 4
    const int bRow = tid >> 5;           // 0..7
    const int bCol = (tid & 31) * 4;     // 0..124
    const int colB = bcol * 128 + bCol;

    const float* Aptr = A + (size_t)(brow * 128 + aRow) * K + aCol;
    const float* Bptr = B + (size_t)bRow * N + colB;

    for (int k0 = 0; k0 < K; k0 += 8) {
        float4 av = *reinterpret_cast<const float4*>(Aptr + k0);
        As[aCol + 0][aRow] = av.x;
        As[aCol + 1][aRow] = av.y;
        As[aCol + 2][aRow] = av.z;
        As[aCol + 3][aRow] = av.w;

        float4 bv = make_float4(0.f, 0.f, 0.f, 0.f);
        if (colB < N)   // N%64==0, colB%4==0 -> colB<N implies colB+4<=N
            bv = *reinterpret_cast<const float4*>(Bptr + (size_t)k0 * N);
        *reinterpret_cast<float4*>(&Bs[bRow][bCol]) = bv;

        __syncthreads();
#pragma unroll
        for (int k = 0; k < 8; k++) {
            float ra[8], rb[8];
#pragma unroll
            for (int i = 0; i < 8; i++) ra[i] = As[k][ty * 8 + i];
#pragma unroll
            for (int j = 0; j < 8; j++) rb[j] = Bs[k][tx * 8 + j];
#pragma unroll
            for (int i = 0; i < 8; i++)
#pragma unroll
                for (int j = 0; j < 8; j++)
                    acc[i][j] += ra[i] * rb[j];
        }
        __syncthreads();
    }

#pragma unroll
    for (int i = 0; i < 8; i++) {
        const int row = brow * 128 + ty * 8 + i;
#pragma unroll
        for (int j = 0; j < 8; j += 4) {
            const int col = bcol * 128 + tx * 8 + j;
            if (col < N) {
                float4 v = make_float4(acc[i][j], acc[i][j + 1],
                                       acc[i][j + 2], acc[i][j + 3]);
                *reinterpret_cast<float4*>(&C[(size_t)row * N + col]) = v;
            }
        }
    }
}

// ---------------- rmsnorm (one block per row) ----------------
__global__ void rmsnorm_kernel(const float* __restrict__ x,
                               const float* __restrict__ gamma,
                               float* __restrict__ y, int D, int xstride)
{
    const int row = blockIdx.x;
    const float* xr = x + (size_t)row * xstride;

    float s = 0.0f;
    for (int i = threadIdx.x; i < D; i += 256) {
        float v = xr[i];
        s += v * v;
    }
    __shared__ float red[256];
    red[threadIdx.x] = s;
    __syncthreads();
    for (int o = 128; o > 0; o >>= 1) {
        if (threadIdx.x < o) red[threadIdx.x] += red[threadIdx.x + o];
        __syncthreads();
    }
    const float inv = rsqrtf(red[0] / (float)D + 1e-6f);
    for (int i = threadIdx.x; i < D; i += 256)
        y[(size_t)row * D + i] = xr[i] * inv * gamma[i];
}

// ---------------- RoPE ----------------
// inv_freq[d] = 10000^(-d/32) = 2^(-d * log2(10000)/32)
__device__ __forceinline__ void rope_cs(int s, int d, float& c, float& sn)
{
    const float inv = exp2f(-(float)d * (13.287712379549449f / 32.0f));
    const float ang = (float)s * inv;
    sincosf(ang, &sn, &c);
}

__global__ void rope_q_kernel(float* __restrict__ q)
{
    const int t = blockIdx.x * blockDim.x + threadIdx.x;
    if (t >= S_LEN * NH * 32) return;
    const int d = t & 31;
    const int h = (t >> 5) & (NH - 1);
    const int s = t >> 12;
    float c, sn;
    rope_cs(s, d, c, sn);
    const size_t base = (size_t)s * QD + (size_t)h * (DN + DR) + DN;
    const float x1 = q[base + d];
    const float x2 = q[base + d + 32];
    q[base + d]      = x1 * c - x2 * sn;
    q[base + d + 32] = x2 * c + x1 * sn;
}

__global__ void rope_k_kernel(const float* __restrict__ comp, float* __restrict__ kpe)
{
    const int t = blockIdx.x * blockDim.x + threadIdx.x;
    if (t >= S_LEN * 32) return;
    const int d = t & 31;
    const int s = t >> 5;
    float c, sn;
    rope_cs(s, d, c, sn);
    const float* src = comp + (size_t)s * COMP_D + QLORA + KVLORA;
    const float x1 = src[d];
    const float x2 = src[d + 32];
    kpe[s * DR + d]      = x1 * c - x2 * sn;
    kpe[s * DR + d + 32] = x2 * c + x1 * sn;
}

// ---------------- scores: attn[h,i,j] = scale * (qn.kn + qpe.kpe), 64x64 tiles ----
__global__ __launch_bounds__(256) void score_kernel(
    const float* __restrict__ q, const float* __restrict__ kv,
    const float* __restrict__ kpe, float* __restrict__ attn)
{
    const int jt = blockIdx.x;
    const int it = blockIdx.y;
    const int h  = blockIdx.z;
    if (jt > it) return;   // fully masked tile: softmax never reads it

    __shared__ float Qs[16][64];
    __shared__ float Ks[16][64];

    const int tid = threadIdx.x;
    const int trow = tid >> 4;   // 0..15
    const int tcol = tid & 15;   // 0..15
    const int li = tid & 63;     // lane within 64
    const int lk = tid >> 6;     // 0..3

    float acc[4][4];
#pragma unroll
    for (int a = 0; a < 4; a++)
#pragma unroll
        for (int b = 0; b < 4; b++) acc[a][b] = 0.0f;

    for (int k0 = 0; k0 < 192; k0 += 16) {
        // Q tile: q rows are contiguous 192 floats per head (nope|pe)
#pragma unroll
        for (int kk = lk; kk < 16; kk += 4) {
            const int kg = k0 + kk;
            const int srow = it * 64 + li;
            Qs[kk][li] = q[(size_t)srow * QD + (size_t)h * 192 + kg];
        }
        // K tile: first 128 from kv nope, last 64 from roped k_pe (shared)
#pragma unroll
        for (int kk = lk; kk < 16; kk += 4) {
            const int kg = k0 + kk;
            const int srow = jt * 64 + li;
            float v;
            if (kg < 128) v = kv[(size_t)srow * KVD + (size_t)h * 256 + kg];
            else          v = kpe[srow * DR + (kg - 128)];
            Ks[kk][li] = v;
        }
        __syncthreads();
#pragma unroll
        for (int k = 0; k < 16; k++) {
            float ri[4], rj[4];
#pragma unroll
            for (int a = 0; a < 4; a++) ri[a] = Qs[k][trow * 4 + a];
#pragma unroll
            for (int b = 0; b < 4; b++) rj[b] = Ks[k][tcol * 4 + b];
#pragma unroll
            for (int a = 0; a < 4; a++)
#pragma unroll
                for (int b = 0; b < 4; b++)
                    acc[a][b] += ri[a] * rj[b];
        }
        __syncthreads();
    }

    const float scale = 0.07216878364870323f;   // 1/sqrt(192)
    const size_t hb = ((size_t)h) << 20;
#pragma unroll
    for (int a = 0; a < 4; a++) {
        const int i = it * 64 + trow * 4 + a;
#pragma unroll
        for (int b = 0; b < 4; b++) {
            const int j = jt * 64 + tcol * 4 + b;
            attn[hb + (size_t)i * 1024 + j] = acc[a][b] * scale;
        }
    }
}

// ---------------- causal softmax per (h, i), in place; zeros for j>i ----------------
__global__ void softmax_kernel(float* __restrict__ attn)
{
    const int i = blockIdx.x;
    const int h = blockIdx.y;
    const size_t base = (((size_t)h) << 20) + (size_t)i * 1024;
    const int len = i + 1;

    __shared__ float red[256];

    float m = -3.4e38f;
    for (int j = threadIdx.x; j < len; j += 256)
        m = fmaxf(m, attn[base + j]);
    red[threadIdx.x] = m;
    __syncthreads();
    for (int o = 128; o > 0; o >>= 1) {
        if (threadIdx.x < o) red[threadIdx.x] = fmaxf(red[threadIdx.x], red[threadIdx.x + o]);
        __syncthreads();
    }
    m = red[0];
    __syncthreads();

    float s = 0.0f;
    for (int j = threadIdx.x; j < len; j += 256)
        s += expf(attn[base + j] - m);
    red[threadIdx.x] = s;
    __syncthreads();
    for (int o = 128; o > 0; o >>= 1) {
        if (threadIdx.x < o) red[threadIdx.x] += red[threadIdx.x + o];
        __syncthreads();
    }
    const float invs = 1.0f / red[0];

    for (int j = threadIdx.x; j < 1024; j += 256) {
        const float v = (j < len) ? expf(attn[base + j] - m) * invs : 0.0f;
        attn[base + j] = v;
    }
}

// ---------------- ctx[i, h*128 + d] = sum_j attn[h,i,j] * v[j,h,d] ----------------
__global__ __launch_bounds__(256) void av_kernel(
    const float* __restrict__ attn, const float* __restrict__ kv,
    float* __restrict__ ctx)
{
    const int dt = blockIdx.x;   // 0..1 (two 64-wide d tiles of 128)
    const int it = blockIdx.y;   // 0..15
    const int h  = blockIdx.z;

    __shared__ float As[16][64];   // [j_local][i_local]
    __shared__ float Vs[16][64];   // [j_local][d_local]

    const int tid = threadIdx.x;
    const int trow = tid >> 4;
    const int tcol = tid & 15;
    const int li = tid & 63;
    const int lk = tid >> 6;

    float acc[4][4];
#pragma unroll
    for (int a = 0; a < 4; a++)
#pragma unroll
        for (int b = 0; b < 4; b++) acc[a][b] = 0.0f;

    const size_t hb = ((size_t)h) << 20;
    const int jend = it * 64 + 64;   // attn is 0 beyond the causal diagonal

    for (int j0 = 0; j0 < jend; j0 += 16) {
#pragma unroll
        for (int kk = lk; kk < 16; kk += 4) {
            As[kk][li] = attn[hb + (size_t)(it * 64 + li) * 1024 + (j0 + kk)];
            Vs[kk][li] = kv[(size_t)(j0 + kk) * KVD + (size_t)h * 256 + 128 + dt * 64 + li];
        }
        __syncthreads();
#pragma unroll
        for (int k = 0; k < 16; k++) {
            float ri[4], rd[4];
#pragma unroll
            for (int a = 0; a < 4; a++) ri[a] = As[k][trow * 4 + a];
#pragma unroll
            for (int b = 0; b < 4; b++) rd[b] = Vs[k][tcol * 4 + b];
#pragma unroll
            for (int a = 0; a < 4; a++)
#pragma unroll
                for (int b = 0; b < 4; b++)
                    acc[a][b] += ri[a] * rd[b];
        }
        __syncthreads();
    }

#pragma unroll
    for (int a = 0; a < 4; a++) {
        const int i = it * 64 + trow * 4 + a;
#pragma unroll
        for (int b = 0; b < 4; b++) {
            const int d = dt * 64 + tcol * 4 + b;
            ctx[(size_t)i * CTX_D + (size_t)h * 128 + d] = acc[a][b];
        }
    }
}

// ---------------- launch ----------------
extern "C" void kernel_launch(void* const* d_in, const int* in_sizes, int n_in,
                              void* d_out, int out_size)
{
    const float* hs       = (const float*)d_in[0];
    const float* w_kv_a   = (const float*)d_in[1];
    const float* q_gamma  = (const float*)d_in[2];
    const float* kv_gamma = (const float*)d_in[3];
    const float* w_q_b    = (const float*)d_in[4];
    const float* w_kv_b   = (const float*)d_in[5];
    const float* w_o      = (const float*)d_in[6];
    float* out = (float*)d_out;

    float *comp, *qn, *kvn, *q, *kv, *kpe, *attn, *ctx;
    cudaGetSymbolAddress((void**)&comp, g_comp);
    cudaGetSymbolAddress((void**)&qn,   g_qn);
    cudaGetSymbolAddress((void**)&kvn,  g_kvn);
    cudaGetSymbolAddress((void**)&q,    g_q);
    cudaGetSymbolAddress((void**)&kv,   g_kv);
    cudaGetSymbolAddress((void**)&kpe,  g_kpe);
    cudaGetSymbolAddress((void**)&attn, g_attn);
    cudaGetSymbolAddress((void**)&ctx,  g_ctx);

    const dim3 T(256);

    // 1) comp = hs @ w_kv_a         (1024 x 7168 x 2112)
    sgemm128<<<dim3((COMP_D + 127) / 128, S_LEN / 128), T>>>(hs, w_kv_a, comp, S_LEN, COMP_D, HID_D);

    // 2) rmsnorm slices
    rmsnorm_kernel<<<S_LEN, 256>>>(comp, q_gamma, qn, QLORA, COMP_D);
    rmsnorm_kernel<<<S_LEN, 256>>>(comp + QLORA, kv_gamma, kvn, KVLORA, COMP_D);

    // 3) q = qn @ w_q_b             (1024 x 1536 x 24576)
    sgemm128<<<dim3(QD / 128, S_LEN / 128), T>>>(qn, w_q_b, q, S_LEN, QD, QLORA);

    // 4) kv = kvn @ w_kv_b          (1024 x 512 x 32768)
    sgemm128<<<dim3(KVD / 128, S_LEN / 128), T>>>(kvn, w_kv_b, kv, S_LEN, KVD, KVLORA);

    // 5) RoPE on q_pe (in place) and k_pe (-> kpe)
    rope_q_kernel<<<(S_LEN * NH * 32) / 256, 256>>>(q);
    rope_k_kernel<<<(S_LEN * 32) / 256, 256>>>(comp, kpe);

    // 6) scores (causal tiles only), softmax, AV
    score_kernel<<<dim3(16, 16, NH), T>>>(q, kv, kpe, attn);
    softmax_kernel<<<dim3(S_LEN, NH), 256>>>(attn);
    av_kernel<<<dim3(2, 16, NH), T>>>(attn, kv, ctx);

    // 7) out = ctx @ w_o            (1024 x 16384 x 7168)
    sgemm128<<<dim3(HID_D / 128, S_LEN / 128), T>>>(ctx, w_o, out, S_LEN, HID_D, CTX_D);
}

// round 3
// speedup vs baseline: 2.2940x; 2.2940x over previous
#include <cuda_runtime.h>
#include <cuda_bf16.h>
#include <math.h>
#include <stdint.h>

// ---------------- problem constants ----------------
#define S_LEN 1024
#define HID_D 7168
#define NH 128
#define DN 128
#define DR 64
#define DV 128
#define QLORA 1536
#define KVLORA 512
#define COMP_D (QLORA + KVLORA + DR)      // 2112
#define QD (NH * (DN + DR))               // 24576
#define KVD (NH * (DN + DV))              // 32768
#define CTX_D (NH * DV)                   // 16384

// ---------------- scratch (device globals) ----------------
__device__ float g_comp[S_LEN * COMP_D];                         // 8.7 MB
__device__ __nv_bfloat16 g_ah[(size_t)S_LEN * 16384];            // 32 MB (activations hi)
__device__ __nv_bfloat16 g_al[(size_t)S_LEN * 16384];            // 32 MB (activations lo)
__device__ __nv_bfloat16 g_wh[117440512];                        // 224 MB (weights hi, transposed)
__device__ __nv_bfloat16 g_wl[117440512];                        // 224 MB (weights lo, transposed)
__device__ float g_q[(size_t)S_LEN * QD];                        // 100 MB
__device__ float g_kv[(size_t)S_LEN * KVD];                      // 134 MB
__device__ float g_kpe[S_LEN * DR];
__device__ float g_attn[(size_t)NH * S_LEN * S_LEN];             // 537 MB

// ---------------- PTX helpers (base sm_103 ISA only) ----------------
__device__ __forceinline__ uint32_t smem_u32(const void* p) {
    uint32_t a;
    asm("{ .reg .u64 t; cvta.to.shared.u64 t, %1; cvt.u32.u64 %0, t; }" : "=r"(a) : "l"(p));
    return a;
}
#define CP16(dst, src) \
    asm volatile("cp.async.cg.shared.global [%0], [%1], 16;" :: "r"(dst), "l"(src) : "memory")
#define CP_COMMIT() asm volatile("cp.async.commit_group;" ::: "memory")
#define CP_WAIT1() asm volatile("cp.async.wait_group 1;" ::: "memory")
#define CP_WAIT0() asm volatile("cp.async.wait_group 0;" ::: "memory")

#define LDSM4(r, a) \
    asm volatile("ldmatrix.sync.aligned.m8n8.x4.shared.b16 {%0,%1,%2,%3}, [%4];" \
        : "=r"((r)[0]), "=r"((r)[1]), "=r"((r)[2]), "=r"((r)[3]) : "r"(a))

#define MMA_BF16(d, a, b0, b1) \
    asm volatile("mma.sync.aligned.m16n8k16.row.col.f32.bf16.bf16.f32 " \
        "{%0,%1,%2,%3}, {%4,%5,%6,%7}, {%8,%9}, {%0,%1,%2,%3};" \
        : "+f"((d)[0]), "+f"((d)[1]), "+f"((d)[2]), "+f"((d)[3]) \
        : "r"((a)[0]), "r"((a)[1]), "r"((a)[2]), "r"((a)[3]), "r"(b0), "r"(b1))

#define SWZ(o) ((o) ^ (((o) >> 3) & 0x70))

// ---------------- warp-MMA split-bf16 GEMM ----------------
// C[M,N] = (Ah+Al)[M,K] @ (Bh+Bl)^T  (Bt stored [Npad,K] K-major).
// 128x128 CTA tile, BK=64, double-buffered cp.async, 8 warps (32x64 each).
// 3 MMA passes: Ah*Bh + Al*Bh + Ah*Bl.
__global__ __launch_bounds__(256, 1) void mma_gemm(
    const __nv_bfloat16* __restrict__ Ah, const __nv_bfloat16* __restrict__ Al,
    const __nv_bfloat16* __restrict__ Bh, const __nv_bfloat16* __restrict__ Bl,
    float* __restrict__ C, int N, int K)
{
    extern __shared__ __align__(128) char smem[];   // 2 stages x 4 tiles x 16KB
    const uint32_t sb = smem_u32(smem);
    const int tid = threadIdx.x;
    const int lane = tid & 31;
    const int wid = tid >> 5;
    const int m0 = blockIdx.y * 128;
    const int n0 = blockIdx.x * 128;
    const int wm = (wid & 3) * 32;
    const int wn = (wid >> 2) * 64;

    float acc[2][8][4];
#pragma unroll
    for (int mt = 0; mt < 2; mt++)
#pragma unroll
        for (int nt = 0; nt < 8; nt++)
#pragma unroll
            for (int e = 0; e < 4; e++) acc[mt][nt][e] = 0.0f;

    const int nch = K >> 6;

    // load one 64-deep K chunk (Ah|Al|Bh|Bl) into stage s
    auto load_stage = [&](int c, int s) {
        const int kc = c << 6;
#pragma unroll
        for (int it = 0; it < 16; it++) {
            const int t = tid + it * 256;           // 0..4095
            const int tensor = t >> 10;             // 0 Ah, 1 Al, 2 Bh, 3 Bl
            const int rem = t & 1023;
            const int row = rem >> 3;
            const int ch = rem & 7;
            const __nv_bfloat16* src;
            int grow;
            if (tensor == 0)      { src = Ah; grow = m0 + row; }
            else if (tensor == 1) { src = Al; grow = m0 + row; }
            else if (tensor == 2) { src = Bh; grow = n0 + row; }
            else                  { src = Bl; grow = n0 + row; }
            const __nv_bfloat16* sp = src + (size_t)grow * K + kc + ch * 8;
            const uint32_t dst = sb + s * 65536 + tensor * 16384 + SWZ(row * 128 + ch * 16);
            CP16(dst, sp);
        }
        CP_COMMIT();
    };

    load_stage(0, 0);

    for (int c = 0; c < nch; c++) {
        const int buf = c & 1;
        if (c + 1 < nch) { load_stage(c + 1, buf ^ 1); CP_WAIT1(); }
        else             { CP_WAIT0(); }
        __syncthreads();

        const uint32_t sA_h = sb + buf * 65536;
        const uint32_t sA_l = sA_h + 16384;
        const uint32_t sB_h = sA_h + 32768;
        const uint32_t sB_l = sA_h + 49152;
        const int rl = lane & 15;        // ldmatrix row-within-16
        const int kb = lane >> 4;        // ldmatrix 16B col block

#pragma unroll
        for (int k16 = 0; k16 < 4; k16++) {
            const int kbyte = k16 * 32 + kb * 16;
            uint32_t afh[2][4], afl[2][4], bfh[4][4], bfl[4][4];
#pragma unroll
            for (int mt = 0; mt < 2; mt++) {
                const uint32_t off = SWZ((wm + mt * 16 + rl) * 128 + kbyte);
                LDSM4(afh[mt], sA_h + off);
                LDSM4(afl[mt], sA_l + off);
            }
#pragma unroll
            for (int q = 0; q < 4; q++) {
                const uint32_t off = SWZ((wn + q * 16 + rl) * 128 + kbyte);
                LDSM4(bfh[q], sB_h + off);
                LDSM4(bfl[q], sB_l + off);
            }
#pragma unroll
            for (int mt = 0; mt < 2; mt++)
#pragma unroll
                for (int nt = 0; nt < 8; nt++) {
                    const int q = nt >> 1, s = nt & 1;
                    MMA_BF16(acc[mt][nt], afh[mt], bfh[q][s], bfh[q][s + 2]);
                    MMA_BF16(acc[mt][nt], afl[mt], bfh[q][s], bfh[q][s + 2]);
                    MMA_BF16(acc[mt][nt], afh[mt], bfl[q][s], bfl[q][s + 2]);
                }
        }
        __syncthreads();
    }

    // epilogue
#pragma unroll
    for (int mt = 0; mt < 2; mt++) {
        const int row = m0 + wm + mt * 16 + (lane >> 2);
#pragma unroll
        for (int nt = 0; nt < 8; nt++) {
            const int col = n0 + wn + nt * 8 + (lane & 3) * 2;
            if (col < N) {
                *reinterpret_cast<float2*>(C + (size_t)row * N + col) =
                    make_float2(acc[mt][nt][0], acc[mt][nt][1]);
                *reinterpret_cast<float2*>(C + (size_t)(row + 8) * N + col) =
                    make_float2(acc[mt][nt][2], acc[mt][nt][3]);
            }
        }
    }
}

// ---------------- weight convert + transpose: W[K,N] fp32 -> T[Npad,K] bf16 hi/lo ----
__global__ void conv_w(const float* __restrict__ W, __nv_bfloat16* __restrict__ Th,
                       __nv_bfloat16* __restrict__ Tl, int K, int N)
{
    __shared__ float t[32][33];
    const int k0 = blockIdx.x * 32, n0 = blockIdx.y * 32;
    const int tx = threadIdx.x, ty = threadIdx.y;
#pragma unroll
    for (int i = 0; i < 4; i++) {
        const int k = k0 + ty + i * 8;
        const int n = n0 + tx;
        t[ty + i * 8][tx] = (n < N) ? W[(size_t)k * N + n] : 0.0f;
    }
    __syncthreads();
#pragma unroll
    for (int i = 0; i < 4; i++) {
        const int n = n0 + ty + i * 8;
        const int k = k0 + tx;
        const float v = t[tx][ty + i * 8];
        const __nv_bfloat16 h = __float2bfloat16(v);
        Th[(size_t)n * K + k] = h;
        Tl[(size_t)n * K + k] = __float2bfloat16(v - __bfloat162float(h));
    }
}

// ---------------- activation convert (fp32 -> bf16 hi/lo) ----------------
__global__ void conv_a(const float* __restrict__ A, __nv_bfloat16* __restrict__ H,
                       __nv_bfloat16* __restrict__ L, int n4)
{
    const int i = blockIdx.x * blockDim.x + threadIdx.x;
    if (i >= n4) return;
    const float4 v = reinterpret_cast<const float4*>(A)[i];
    __nv_bfloat16 h0 = __float2bfloat16(v.x), h1 = __float2bfloat16(v.y);
    __nv_bfloat16 h2 = __float2bfloat16(v.z), h3 = __float2bfloat16(v.w);
    __nv_bfloat162* Hp = reinterpret_cast<__nv_bfloat162*>(H) + i * 2;
    __nv_bfloat162* Lp = reinterpret_cast<__nv_bfloat162*>(L) + i * 2;
    Hp[0] = __nv_bfloat162(h0, h1);
    Hp[1] = __nv_bfloat162(h2, h3);
    Lp[0] = __nv_bfloat162(__float2bfloat16(v.x - __bfloat162float(h0)),
                           __float2bfloat16(v.y - __bfloat162float(h1)));
    Lp[1] = __nv_bfloat162(__float2bfloat16(v.z - __bfloat162float(h2)),
                           __float2bfloat16(v.w - __bfloat162float(h3)));
}

// ---------------- rmsnorm fused to bf16 hi/lo ----------------
__global__ void rmsnorm_bf16(const float* __restrict__ x, const float* __restrict__ gamma,
                             __nv_bfloat16* __restrict__ yh, __nv_bfloat16* __restrict__ yl,
                             int D, int xstride)
{
    const int row = blockIdx.x;
    const float* xr = x + (size_t)row * xstride;
    float s = 0.0f;
    for (int i = threadIdx.x; i < D; i += 256) { const float v = xr[i]; s += v * v; }
    __shared__ float red[256];
    red[threadIdx.x] = s;
    __syncthreads();
    for (int o = 128; o > 0; o >>= 1) {
        if (threadIdx.x < o) red[threadIdx.x] += red[threadIdx.x + o];
        __syncthreads();
    }
    const float inv = rsqrtf(red[0] / (float)D + 1e-6f);
    for (int i = threadIdx.x; i < D; i += 256) {
        const float v = xr[i] * inv * gamma[i];
        const __nv_bfloat16 h = __float2bfloat16(v);
        yh[(size_t)row * D + i] = h;
        yl[(size_t)row * D + i] = __float2bfloat16(v - __bfloat162float(h));
    }
}

// ---------------- RoPE ----------------
__device__ __forceinline__ void rope_cs(int s, int d, float& c, float& sn)
{
    const float inv = exp2f(-(float)d * (13.287712379549449f / 32.0f));
    sincosf((float)s * inv, &sn, &c);
}

__global__ void rope_q_kernel(float* __restrict__ q)
{
    const int t = blockIdx.x * blockDim.x + threadIdx.x;
    if (t >= S_LEN * NH * 32) return;
    const int d = t & 31;
    const int h = (t >> 5) & (NH - 1);
    const int s = t >> 12;
    float c, sn;
    rope_cs(s, d, c, sn);
    const size_t base = (size_t)s * QD + (size_t)h * (DN + DR) + DN;
    const float x1 = q[base + d], x2 = q[base + d + 32];
    q[base + d]      = x1 * c - x2 * sn;
    q[base + d + 32] = x2 * c + x1 * sn;
}

__global__ void rope_k_kernel(const float* __restrict__ comp, float* __restrict__ kpe)
{
    const int t = blockIdx.x * blockDim.x + threadIdx.x;
    if (t >= S_LEN * 32) return;
    const int d = t & 31;
    const int s = t >> 5;
    float c, sn;
    rope_cs(s, d, c, sn);
    const float* src = comp + (size_t)s * COMP_D + QLORA + KVLORA;
    const float x1 = src[d], x2 = src[d + 32];
    kpe[s * DR + d]      = x1 * c - x2 * sn;
    kpe[s * DR + d + 32] = x2 * c + x1 * sn;
}

// ---------------- attention (fp32 CUDA-core, R1-proven) ----------------
__global__ __launch_bounds__(256) void score_kernel(
    const float* __restrict__ q, const float* __restrict__ kv,
    const float* __restrict__ kpe, float* __restrict__ attn)
{
    const int jt = blockIdx.x, it = blockIdx.y, h = blockIdx.z;
    if (jt > it) return;
    __shared__ float Qs[16][64];
    __shared__ float Ks[16][64];
    const int tid = threadIdx.x;
    const int trow = tid >> 4, tcol = tid & 15;
    const int li = tid & 63, lk = tid >> 6;
    float acc[4][4];
#pragma unroll
    for (int a = 0; a < 4; a++)
#pragma unroll
        for (int b = 0; b < 4; b++) acc[a][b] = 0.0f;

    for (int k0 = 0; k0 < 192; k0 += 16) {
#pragma unroll
        for (int kk = lk; kk < 16; kk += 4) {
            const int kg = k0 + kk;
            Qs[kk][li] = q[(size_t)(it * 64 + li) * QD + (size_t)h * 192 + kg];
            const int srow = jt * 64 + li;
            Ks[kk][li] = (kg < 128) ? kv[(size_t)srow * KVD + (size_t)h * 256 + kg]
                                    : kpe[srow * DR + (kg - 128)];
        }
        __syncthreads();
#pragma unroll
        for (int k = 0; k < 16; k++) {
            float ri[4], rj[4];
#pragma unroll
            for (int a = 0; a < 4; a++) ri[a] = Qs[k][trow * 4 + a];
#pragma unroll
            for (int b = 0; b < 4; b++) rj[b] = Ks[k][tcol * 4 + b];
#pragma unroll
            for (int a = 0; a < 4; a++)
#pragma unroll
                for (int b = 0; b < 4; b++) acc[a][b] += ri[a] * rj[b];
        }
        __syncthreads();
    }
    const float scale = 0.07216878364870323f;
    const size_t hb = ((size_t)h) << 20;
#pragma unroll
    for (int a = 0; a < 4; a++) {
        const int i = it * 64 + trow * 4 + a;
#pragma unroll
        for (int b = 0; b < 4; b++) {
            const int j = jt * 64 + tcol * 4 + b;
            attn[hb + (size_t)i * 1024 + j] = acc[a][b] * scale;
        }
    }
}

__global__ void softmax_kernel(float* __restrict__ attn)
{
    const int i = blockIdx.x, h = blockIdx.y;
    const size_t base = (((size_t)h) << 20) + (size_t)i * 1024;
    const int len = i + 1;
    __shared__ float red[256];
    float m = -3.4e38f;
    for (int j = threadIdx.x; j < len; j += 256) m = fmaxf(m, attn[base + j]);
    red[threadIdx.x] = m;
    __syncthreads();
    for (int o = 128; o > 0; o >>= 1) {
        if (threadIdx.x < o) red[threadIdx.x] = fmaxf(red[threadIdx.x], red[threadIdx.x + o]);
        __syncthreads();
    }
    m = red[0];
    __syncthreads();
    float s = 0.0f;
    for (int j = threadIdx.x; j < len; j += 256) s += expf(attn[base + j] - m);
    red[threadIdx.x] = s;
    __syncthreads();
    for (int o = 128; o > 0; o >>= 1) {
        if (threadIdx.x < o) red[threadIdx.x] += red[threadIdx.x + o];
        __syncthreads();
    }
    const float invs = 1.0f / red[0];
    for (int j = threadIdx.x; j < 1024; j += 256)
        attn[base + j] = (j < len) ? expf(attn[base + j] - m) * invs : 0.0f;
}

__global__ __launch_bounds__(256) void av_kernel(
    const float* __restrict__ attn, const float* __restrict__ kv,
    __nv_bfloat16* __restrict__ ch, __nv_bfloat16* __restrict__ cl)
{
    const int dt = blockIdx.x, it = blockIdx.y, h = blockIdx.z;
    __shared__ float As[16][64];
    __shared__ float Vs[16][64];
    const int tid = threadIdx.x;
    const int trow = tid >> 4, tcol = tid & 15;
    const int li = tid & 63, lk = tid >> 6;
    float acc[4][4];
#pragma unroll
    for (int a = 0; a < 4; a++)
#pragma unroll
        for (int b = 0; b < 4; b++) acc[a][b] = 0.0f;
    const size_t hb = ((size_t)h) << 20;
    const int jend = it * 64 + 64;
    for (int j0 = 0; j0 < jend; j0 += 16) {
#pragma unroll
        for (int kk = lk; kk < 16; kk += 4) {
            As[kk][li] = attn[hb + (size_t)(it * 64 + li) * 1024 + (j0 + kk)];
            Vs[kk][li] = kv[(size_t)(j0 + kk) * KVD + (size_t)h * 256 + 128 + dt * 64 + li];
        }
        __syncthreads();
#pragma unroll
        for (int k = 0; k < 16; k++) {
            float ri[4], rd[4];
#pragma unroll
            for (int a = 0; a < 4; a++) ri[a] = As[k][trow * 4 + a];
#pragma unroll
            for (int b = 0; b < 4; b++) rd[b] = Vs[k][tcol * 4 + b];
#pragma unroll
            for (int a = 0; a < 4; a++)
#pragma unroll
                for (int b = 0; b < 4; b++) acc[a][b] += ri[a] * rd[b];
        }
        __syncthreads();
    }
#pragma unroll
    for (int a = 0; a < 4; a++) {
        const int i = it * 64 + trow * 4 + a;
#pragma unroll
        for (int b = 0; b < 4; b++) {
            const int d = dt * 64 + tcol * 4 + b;
            const size_t o = (size_t)i * CTX_D + (size_t)h * 128 + d;
            const float v = acc[a][b];
            const __nv_bfloat16 hh = __float2bfloat16(v);
            ch[o] = hh;
            cl[o] = __float2bfloat16(v - __bfloat162float(hh));
        }
    }
}

// ---------------- launch ----------------
extern "C" void kernel_launch(void* const* d_in, const int* in_sizes, int n_in,
                              void* d_out, int out_size)
{
    const float* hs       = (const float*)d_in[0];
    const float* w_kv_a   = (const float*)d_in[1];
    const float* q_gamma  = (const float*)d_in[2];
    const float* kv_gamma = (const float*)d_in[3];
    const float* w_q_b    = (const float*)d_in[4];
    const float* w_kv_b   = (const float*)d_in[5];
    const float* w_o      = (const float*)d_in[6];
    float* out = (float*)d_out;

    float *comp, *q, *kv, *kpe, *attn;
    __nv_bfloat16 *ah, *al, *wh, *wl;
    cudaGetSymbolAddress((void**)&comp, g_comp);
    cudaGetSymbolAddress((void**)&ah,   g_ah);
    cudaGetSymbolAddress((void**)&al,   g_al);
    cudaGetSymbolAddress((void**)&wh,   g_wh);
    cudaGetSymbolAddress((void**)&wl,   g_wl);
    cudaGetSymbolAddress((void**)&q,    g_q);
    cudaGetSymbolAddress((void**)&kv,   g_kv);
    cudaGetSymbolAddress((void**)&kpe,  g_kpe);
    cudaGetSymbolAddress((void**)&attn, g_attn);

    cudaFuncSetAttribute(mma_gemm, cudaFuncAttributeMaxDynamicSharedMemorySize, 131072);
    const int GSM = 131072;
    const dim3 T256(256);
    const dim3 TW(32, 8);

    // 1) comp = hs @ w_kv_a  (M=1024, N=2112 (pad 2176), K=7168)
    conv_a<<<(S_LEN * HID_D / 4 + 255) / 256, 256>>>(hs, ah, al, S_LEN * HID_D / 4);
    conv_w<<<dim3(HID_D / 32, 2176 / 32), TW>>>(w_kv_a, wh, wl, HID_D, COMP_D);
    mma_gemm<<<dim3(17, 8), T256, GSM>>>(ah, al, wh, wl, comp, COMP_D, HID_D);

    // 2) k_pe RoPE (reads comp)
    rope_k_kernel<<<(S_LEN * 32) / 256, 256>>>(comp, kpe);

    // 3) q = rmsnorm(q_c) @ w_q_b  (M=1024, N=24576, K=1536)
    rmsnorm_bf16<<<S_LEN, 256>>>(comp, q_gamma, ah, al, QLORA, COMP_D);
    conv_w<<<dim3(QLORA / 32, QD / 32), TW>>>(w_q_b, wh, wl, QLORA, QD);
    mma_gemm<<<dim3(QD / 128, 8), T256, GSM>>>(ah, al, wh, wl, q, QD, QLORA);
    rope_q_kernel<<<(S_LEN * NH * 32) / 256, 256>>>(q);

    // 4) kv = rmsnorm(kv_c) @ w_kv_b  (M=1024, N=32768, K=512)
    rmsnorm_bf16<<<S_LEN, 256>>>(comp + QLORA, kv_gamma, ah, al, KVLORA, COMP_D);
    conv_w<<<dim3(KVLORA / 32, KVD / 32), TW>>>(w_kv_b, wh, wl, KVLORA, KVD);
    mma_gemm<<<dim3(KVD / 128, 8), T256, GSM>>>(ah, al, wh, wl, kv, KVD, KVLORA);

    // 5) attention (fp32)
    score_kernel<<<dim3(16, 16, NH), T256>>>(q, kv, kpe, attn);
    softmax_kernel<<<dim3(S_LEN, NH), 256>>>(attn);
    av_kernel<<<dim3(2, 16, NH), T256>>>(attn, kv, ah, al);   // ctx -> bf16 pair

    // 6) out = ctx @ w_o  (M=1024, N=7168, K=16384)
    conv_w<<<dim3(CTX_D / 32, HID_D / 32), TW>>>(w_o, wh, wl, CTX_D, HID_D);
    mma_gemm<<<dim3(HID_D / 128, 8), T256, GSM>>>(ah, al, wh, wl, out, HID_D, CTX_D);
}

// round 4
// speedup vs baseline: 3.6497x; 1.5909x over previous
#include <cuda_runtime.h>
#include <cuda_bf16.h>
#include <math.h>
#include <stdint.h>

// ---------------- problem constants ----------------
#define S_LEN 1024
#define HID_D 7168
#define NH 128
#define DN 128
#define DR 64
#define DV 128
#define QLORA 1536
#define KVLORA 512
#define COMP_D (QLORA + KVLORA + DR)      // 2112
#define QD (NH * (DN + DR))               // 24576
#define KVD (NH * (DN + DV))              // 32768
#define CTX_D (NH * DV)                   // 16384
#define DQK 192

// ---------------- scratch (device globals) ----------------
__device__ float g_comp[S_LEN * COMP_D];
__device__ __nv_bfloat16 g_ah[(size_t)S_LEN * 16384];
__device__ __nv_bfloat16 g_al[(size_t)S_LEN * 16384];
__device__ __nv_bfloat16 g_wh[117440512];
__device__ __nv_bfloat16 g_wl[117440512];
__device__ float g_q[(size_t)S_LEN * QD];
__device__ float g_kv[(size_t)S_LEN * KVD];
__device__ float g_kpe[S_LEN * DR];
__device__ float g_attn[(size_t)NH * S_LEN * S_LEN];             // 537 MB
// attention staging
__device__ __nv_bfloat16 g_qh[(size_t)NH * S_LEN * DQK];         // 50 MB
__device__ __nv_bfloat16 g_ql[(size_t)NH * S_LEN * DQK];
__device__ __nv_bfloat16 g_kh[(size_t)NH * S_LEN * DQK];
__device__ __nv_bfloat16 g_kl[(size_t)NH * S_LEN * DQK];
__device__ __nv_bfloat16 g_vth[(size_t)NH * DV * S_LEN];         // 33.5 MB
__device__ __nv_bfloat16 g_vtl[(size_t)NH * DV * S_LEN];
__device__ __nv_bfloat16 g_ph[(size_t)NH * S_LEN * S_LEN];       // 268 MB
__device__ __nv_bfloat16 g_pl[(size_t)NH * S_LEN * S_LEN];
__device__ float g_inv[NH * S_LEN];

// ---------------- PTX helpers (base sm_103 ISA only) ----------------
__device__ __forceinline__ uint32_t smem_u32(const void* p) {
    uint32_t a;
    asm("{ .reg .u64 t; cvta.to.shared.u64 t, %1; cvt.u32.u64 %0, t; }" : "=r"(a) : "l"(p));
    return a;
}
#define CP16(dst, src) \
    asm volatile("cp.async.cg.shared.global [%0], [%1], 16;" :: "r"(dst), "l"(src) : "memory")
#define CP_COMMIT() asm volatile("cp.async.commit_group;" ::: "memory")
#define CP_WAIT1() asm volatile("cp.async.wait_group 1;" ::: "memory")
#define CP_WAIT0() asm volatile("cp.async.wait_group 0;" ::: "memory")

#define LDSM4(r, a) \
    asm volatile("ldmatrix.sync.aligned.m8n8.x4.shared.b16 {%0,%1,%2,%3}, [%4];" \
        : "=r"((r)[0]), "=r"((r)[1]), "=r"((r)[2]), "=r"((r)[3]) : "r"(a))

#define MMA_BF16(d, a, b0, b1) \
    asm volatile("mma.sync.aligned.m16n8k16.row.col.f32.bf16.bf16.f32 " \
        "{%0,%1,%2,%3}, {%4,%5,%6,%7}, {%8,%9}, {%0,%1,%2,%3};" \
        : "+f"((d)[0]), "+f"((d)[1]), "+f"((d)[2]), "+f"((d)[3]) \
        : "r"((a)[0]), "r"((a)[1]), "r"((a)[2]), "r"((a)[3]), "r"(b0), "r"(b1))

#define SWZ(o) ((o) ^ (((o) >> 3) & 0x70))

// ---------------- shared GEMM body: acc += 3-pass split-bf16 128x128 tile ------
// A rows at Ah/Al + (m0+row)*K, B rows at Bh/Bl + (n0+row)*K. nch chunks of 64.
__device__ __forceinline__ void gemm_body(
    const __nv_bfloat16* __restrict__ Ah, const __nv_bfloat16* __restrict__ Al,
    const __nv_bfloat16* __restrict__ Bh, const __nv_bfloat16* __restrict__ Bl,
    int K, int nch, int m0, int n0, uint32_t sb, int tid, float acc[2][8][4])
{
    const int lane = tid & 31;
    const int wid = tid >> 5;
    const int wm = (wid & 3) * 32;
    const int wn = (wid >> 2) * 64;

    auto load_stage = [&](int c, int s) {
        const int kc = c << 6;
#pragma unroll
        for (int it = 0; it < 16; it++) {
            const int t = tid + it * 256;
            const int tensor = t >> 10;
            const int rem = t & 1023;
            const int row = rem >> 3;
            const int ch = rem & 7;
            const __nv_bfloat16* src;
            int grow;
            if (tensor == 0)      { src = Ah; grow = m0 + row; }
            else if (tensor == 1) { src = Al; grow = m0 + row; }
            else if (tensor == 2) { src = Bh; grow = n0 + row; }
            else                  { src = Bl; grow = n0 + row; }
            const __nv_bfloat16* sp = src + (size_t)grow * K + kc + ch * 8;
            const uint32_t dst = sb + s * 65536 + tensor * 16384 + SWZ(row * 128 + ch * 16);
            CP16(dst, sp);
        }
        CP_COMMIT();
    };

    load_stage(0, 0);

    for (int c = 0; c < nch; c++) {
        const int buf = c & 1;
        if (c + 1 < nch) { load_stage(c + 1, buf ^ 1); CP_WAIT1(); }
        else             { CP_WAIT0(); }
        __syncthreads();

        const uint32_t sA_h = sb + buf * 65536;
        const uint32_t sA_l = sA_h + 16384;
        const uint32_t sB_h = sA_h + 32768;
        const uint32_t sB_l = sA_h + 49152;
        const int rl = lane & 15;
        const int kb = lane >> 4;

#pragma unroll
        for (int k16 = 0; k16 < 4; k16++) {
            const int kbyte = k16 * 32 + kb * 16;
            uint32_t afh[2][4], afl[2][4], bfh[4][4], bfl[4][4];
#pragma unroll
            for (int mt = 0; mt < 2; mt++) {
                const uint32_t off = SWZ((wm + mt * 16 + rl) * 128 + kbyte);
                LDSM4(afh[mt], sA_h + off);
                LDSM4(afl[mt], sA_l + off);
            }
#pragma unroll
            for (int q = 0; q < 4; q++) {
                const uint32_t off = SWZ((wn + q * 16 + rl) * 128 + kbyte);
                LDSM4(bfh[q], sB_h + off);
                LDSM4(bfl[q], sB_l + off);
            }
#pragma unroll
            for (int mt = 0; mt < 2; mt++)
#pragma unroll
                for (int nt = 0; nt < 8; nt++) {
                    const int q = nt >> 1, s = nt & 1;
                    MMA_BF16(acc[mt][nt], afh[mt], bfh[q][s], bfh[q][s + 2]);
                    MMA_BF16(acc[mt][nt], afl[mt], bfh[q][s], bfh[q][s + 2]);
                    MMA_BF16(acc[mt][nt], afh[mt], bfl[q][s], bfl[q][s + 2]);
                }
        }
        __syncthreads();
    }
}

// ---------------- dense GEMM (weights path, unchanged semantics) ----------------
__global__ __launch_bounds__(256, 1) void mma_gemm(
    const __nv_bfloat16* __restrict__ Ah, const __nv_bfloat16* __restrict__ Al,
    const __nv_bfloat16* __restrict__ Bh, const __nv_bfloat16* __restrict__ Bl,
    float* __restrict__ C, int N, int K)
{
    extern __shared__ __align__(128) char smem[];
    const uint32_t sb = smem_u32(smem);
    const int tid = threadIdx.x;
    const int lane = tid & 31;
    const int wid = tid >> 5;
    const int m0 = blockIdx.y * 128, n0 = blockIdx.x * 128;
    const int wm = (wid & 3) * 32, wn = (wid >> 2) * 64;

    float acc[2][8][4];
#pragma unroll
    for (int mt = 0; mt < 2; mt++)
#pragma unroll
        for (int nt = 0; nt < 8; nt++)
#pragma unroll
            for (int e = 0; e < 4; e++) acc[mt][nt][e] = 0.0f;

    gemm_body(Ah, Al, Bh, Bl, K, K >> 6, m0, n0, sb, tid, acc);

#pragma unroll
    for (int mt = 0; mt < 2; mt++) {
        const int row = m0 + wm + mt * 16 + (lane >> 2);
#pragma unroll
        for (int nt = 0; nt < 8; nt++) {
            const int col = n0 + wn + nt * 8 + (lane & 3) * 2;
            if (col < N) {
                *reinterpret_cast<float2*>(C + (size_t)row * N + col) =
                    make_float2(acc[mt][nt][0], acc[mt][nt][1]);
                *reinterpret_cast<float2*>(C + (size_t)(row + 8) * N + col) =
                    make_float2(acc[mt][nt][2], acc[mt][nt][3]);
            }
        }
    }
}

// ---------------- score GEMM: attn[h] = scale * Qh[h] @ Kh[h]^T ----------------
__global__ __launch_bounds__(256, 1) void score_mma(
    const __nv_bfloat16* __restrict__ Qh, const __nv_bfloat16* __restrict__ Ql,
    const __nv_bfloat16* __restrict__ Kh, const __nv_bfloat16* __restrict__ Kl,
    float* __restrict__ attn)
{
    const int jt = blockIdx.x, it = blockIdx.y, h = blockIdx.z;
    if (jt > it) return;
    extern __shared__ __align__(128) char smem[];
    const uint32_t sb = smem_u32(smem);
    const int tid = threadIdx.x;
    const int lane = tid & 31;
    const int wid = tid >> 5;
    const int m0 = it * 128, n0 = jt * 128;
    const int wm = (wid & 3) * 32, wn = (wid >> 2) * 64;
    const size_t hoff = (size_t)h * S_LEN * DQK;

    float acc[2][8][4];
#pragma unroll
    for (int mt = 0; mt < 2; mt++)
#pragma unroll
        for (int nt = 0; nt < 8; nt++)
#pragma unroll
            for (int e = 0; e < 4; e++) acc[mt][nt][e] = 0.0f;

    gemm_body(Qh + hoff, Ql + hoff, Kh + hoff, Kl + hoff, DQK, 3, m0, n0, sb, tid, acc);

    const float scale = 0.07216878364870323f;   // 1/sqrt(192)
    float* C = attn + (((size_t)h) << 20);
#pragma unroll
    for (int mt = 0; mt < 2; mt++) {
        const int row = m0 + wm + mt * 16 + (lane >> 2);
#pragma unroll
        for (int nt = 0; nt < 8; nt++) {
            const int col = n0 + wn + nt * 8 + (lane & 3) * 2;
            *reinterpret_cast<float2*>(C + (size_t)row * S_LEN + col) =
                make_float2(acc[mt][nt][0] * scale, acc[mt][nt][1] * scale);
            *reinterpret_cast<float2*>(C + (size_t)(row + 8) * S_LEN + col) =
                make_float2(acc[mt][nt][2] * scale, acc[mt][nt][3] * scale);
        }
    }
}

// ---------------- AV GEMM: ctx[h] = (P[h] @ Vt[h]^T) * inv_sum, split bf16 out ---
__global__ __launch_bounds__(256, 1) void av_mma(
    const __nv_bfloat16* __restrict__ Ph, const __nv_bfloat16* __restrict__ Pl,
    const __nv_bfloat16* __restrict__ Vth, const __nv_bfloat16* __restrict__ Vtl,
    const float* __restrict__ inv_sum,
    __nv_bfloat16* __restrict__ ch, __nv_bfloat16* __restrict__ cl)
{
    const int it = blockIdx.y, h = blockIdx.z;
    extern __shared__ __align__(128) char smem[];
    const uint32_t sb = smem_u32(smem);
    const int tid = threadIdx.x;
    const int lane = tid & 31;
    const int wid = tid >> 5;
    const int m0 = it * 128;
    const int wm = (wid & 3) * 32, wn = (wid >> 2) * 64;

    float acc[2][8][4];
#pragma unroll
    for (int mt = 0; mt < 2; mt++)
#pragma unroll
        for (int nt = 0; nt < 8; nt++)
#pragma unroll
            for (int e = 0; e < 4; e++) acc[mt][nt][e] = 0.0f;

    const size_t poff = ((size_t)h) << 20;
    const size_t voff = (size_t)h * DV * S_LEN;
    gemm_body(Ph + poff, Pl + poff, Vth + voff, Vtl + voff,
              S_LEN, (it + 1) * 2, m0, 0, sb, tid, acc);

#pragma unroll
    for (int mt = 0; mt < 2; mt++) {
#pragma unroll
        for (int half = 0; half < 2; half++) {
            const int row = m0 + wm + mt * 16 + (lane >> 2) + half * 8;
            const float inv = inv_sum[h * S_LEN + row];
#pragma unroll
            for (int nt = 0; nt < 8; nt++) {
                const int col = wn + nt * 8 + (lane & 3) * 2;
                const size_t o = (size_t)row * CTX_D + (size_t)h * DV + col;
                const float v0 = acc[mt][nt][half * 2] * inv;
                const float v1 = acc[mt][nt][half * 2 + 1] * inv;
                const __nv_bfloat16 h0 = __float2bfloat16(v0);
                const __nv_bfloat16 h1 = __float2bfloat16(v1);
                *reinterpret_cast<__nv_bfloat162*>(ch + o) = __nv_bfloat162(h0, h1);
                *reinterpret_cast<__nv_bfloat162*>(cl + o) =
                    __nv_bfloat162(__float2bfloat16(v0 - __bfloat162float(h0)),
                                   __float2bfloat16(v1 - __bfloat162float(h1)));
            }
        }
    }
}

// ---------------- weight convert + transpose ----------------
__global__ void conv_w(const float* __restrict__ W, __nv_bfloat16* __restrict__ Th,
                       __nv_bfloat16* __restrict__ Tl, int K, int N)
{
    __shared__ float t[32][33];
    const int k0 = blockIdx.x * 32, n0 = blockIdx.y * 32;
    const int tx = threadIdx.x, ty = threadIdx.y;
#pragma unroll
    for (int i = 0; i < 4; i++) {
        const int k = k0 + ty + i * 8;
        const int n = n0 + tx;
        t[ty + i * 8][tx] = (n < N) ? W[(size_t)k * N + n] : 0.0f;
    }
    __syncthreads();
#pragma unroll
    for (int i = 0; i < 4; i++) {
        const int n = n0 + ty + i * 8;
        const int k = k0 + tx;
        const float v = t[tx][ty + i * 8];
        const __nv_bfloat16 h = __float2bfloat16(v);
        Th[(size_t)n * K + k] = h;
        Tl[(size_t)n * K + k] = __float2bfloat16(v - __bfloat162float(h));
    }
}

// ---------------- activation convert ----------------
__global__ void conv_a(const float* __restrict__ A, __nv_bfloat16* __restrict__ H,
                       __nv_bfloat16* __restrict__ L, int n4)
{
    const int i = blockIdx.x * blockDim.x + threadIdx.x;
    if (i >= n4) return;
    const float4 v = reinterpret_cast<const float4*>(A)[i];
    __nv_bfloat16 h0 = __float2bfloat16(v.x), h1 = __float2bfloat16(v.y);
    __nv_bfloat16 h2 = __float2bfloat16(v.z), h3 = __float2bfloat16(v.w);
    __nv_bfloat162* Hp = reinterpret_cast<__nv_bfloat162*>(H) + i * 2;
    __nv_bfloat162* Lp = reinterpret_cast<__nv_bfloat162*>(L) + i * 2;
    Hp[0] = __nv_bfloat162(h0, h1);
    Hp[1] = __nv_bfloat162(h2, h3);
    Lp[0] = __nv_bfloat162(__float2bfloat16(v.x - __bfloat162float(h0)),
                           __float2bfloat16(v.y - __bfloat162float(h1)));
    Lp[1] = __nv_bfloat162(__float2bfloat16(v.z - __bfloat162float(h2)),
                           __float2bfloat16(v.w - __bfloat162float(h3)));
}

// ---------------- rmsnorm fused to bf16 hi/lo ----------------
__global__ void rmsnorm_bf16(const float* __restrict__ x, const float* __restrict__ gamma,
                             __nv_bfloat16* __restrict__ yh, __nv_bfloat16* __restrict__ yl,
                             int D, int xstride)
{
    const int row = blockIdx.x;
    const float* xr = x + (size_t)row * xstride;
    float s = 0.0f;
    for (int i = threadIdx.x; i < D; i += 256) { const float v = xr[i]; s += v * v; }
    __shared__ float red[256];
    red[threadIdx.x] = s;
    __syncthreads();
    for (int o = 128; o > 0; o >>= 1) {
        if (threadIdx.x < o) red[threadIdx.x] += red[threadIdx.x + o];
        __syncthreads();
    }
    const float inv = rsqrtf(red[0] / (float)D + 1e-6f);
    for (int i = threadIdx.x; i < D; i += 256) {
        const float v = xr[i] * inv * gamma[i];
        const __nv_bfloat16 h = __float2bfloat16(v);
        yh[(size_t)row * D + i] = h;
        yl[(size_t)row * D + i] = __float2bfloat16(v - __bfloat162float(h));
    }
}

// ---------------- RoPE helpers ----------------
__device__ __forceinline__ void rope_cs(int s, int d, float& c, float& sn)
{
    const float inv = exp2f(-(float)d * (13.287712379549449f / 32.0f));
    sincosf((float)s * inv, &sn, &c);
}

__global__ void rope_k_kernel(const float* __restrict__ comp, float* __restrict__ kpe)
{
    const int t = blockIdx.x * blockDim.x + threadIdx.x;
    if (t >= S_LEN * 32) return;
    const int d = t & 31;
    const int s = t >> 5;
    float c, sn;
    rope_cs(s, d, c, sn);
    const float* src = comp + (size_t)s * COMP_D + QLORA + KVLORA;
    const float x1 = src[d], x2 = src[d + 32];
    kpe[s * DR + d]      = x1 * c - x2 * sn;
    kpe[s * DR + d + 32] = x2 * c + x1 * sn;
}

// ---------------- build Q per head (gather + RoPE + split) ----------------
// q fp32 [i][h*192 + c]  ->  Qh/Ql [h][i][192]
__global__ void build_q(const float* __restrict__ q,
                        __nv_bfloat16* __restrict__ Qh, __nv_bfloat16* __restrict__ Ql)
{
    const int t = blockIdx.x * blockDim.x + threadIdx.x;
    if (t >= NH * S_LEN * 48) return;
    const int c4 = t % 48;
    const int i  = (t / 48) & (S_LEN - 1);
    const int h  = t / (48 * S_LEN);

    const float* src = q + (size_t)i * QD + h * DQK;
    float4 v;
    if (c4 < 32) {
        v = *reinterpret_cast<const float4*>(src + c4 * 4);
    } else {
        const int d0 = (c4 - 32) * 4;              // 0..60, block of 4 pe dims
        const float4 a = *reinterpret_cast<const float4*>(src + DN + d0);
        const float4 b = *reinterpret_cast<const float4*>(src + DN + (d0 ^ 32));
        const float* ap = &a.x;
        const float* bp = &b.x;
        float* vp = &v.x;
#pragma unroll
        for (int e = 0; e < 4; e++) {
            const int d = d0 + e;
            float c, sn;
            rope_cs(i, d & 31, c, sn);
            vp[e] = (d < 32) ? (ap[e] * c - bp[e] * sn)
                             : (ap[e] * c + bp[e] * sn);
        }
    }
    const size_t o = ((size_t)h * S_LEN + i) * DQK + c4 * 4;
    __nv_bfloat16 h0 = __float2bfloat16(v.x), h1 = __float2bfloat16(v.y);
    __nv_bfloat16 h2 = __float2bfloat16(v.z), h3 = __float2bfloat16(v.w);
    *reinterpret_cast<__nv_bfloat162*>(Qh + o)     = __nv_bfloat162(h0, h1);
    *reinterpret_cast<__nv_bfloat162*>(Qh + o + 2) = __nv_bfloat162(h2, h3);
    *reinterpret_cast<__nv_bfloat162*>(Ql + o) =
        __nv_bfloat162(__float2bfloat16(v.x - __bfloat162float(h0)),
                       __float2bfloat16(v.y - __bfloat162float(h1)));
    *reinterpret_cast<__nv_bfloat162*>(Ql + o + 2) =
        __nv_bfloat162(__float2bfloat16(v.z - __bfloat162float(h2)),
                       __float2bfloat16(v.w - __bfloat162float(h3)));
}

// ---------------- build K per head (kv nope + shared roped kpe, split) ----------
__global__ void build_k(const float* __restrict__ kv, const float* __restrict__ kpe,
                        __nv_bfloat16* __restrict__ Kh, __nv_bfloat16* __restrict__ Kl)
{
    const int t = blockIdx.x * blockDim.x + threadIdx.x;
    if (t >= NH * S_LEN * 48) return;
    const int c4 = t % 48;
    const int j  = (t / 48) & (S_LEN - 1);
    const int h  = t / (48 * S_LEN);

    float4 v;
    if (c4 < 32) v = *reinterpret_cast<const float4*>(kv + (size_t)j * KVD + h * 256 + c4 * 4);
    else         v = *reinterpret_cast<const float4*>(kpe + j * DR + (c4 - 32) * 4);

    const size_t o = ((size_t)h * S_LEN + j) * DQK + c4 * 4;
    __nv_bfloat16 h0 = __float2bfloat16(v.x), h1 = __float2bfloat16(v.y);
    __nv_bfloat16 h2 = __float2bfloat16(v.z), h3 = __float2bfloat16(v.w);
    *reinterpret_cast<__nv_bfloat162*>(Kh + o)     = __nv_bfloat162(h0, h1);
    *reinterpret_cast<__nv_bfloat162*>(Kh + o + 2) = __nv_bfloat162(h2, h3);
    *reinterpret_cast<__nv_bfloat162*>(Kl + o) =
        __nv_bfloat162(__float2bfloat16(v.x - __bfloat162float(h0)),
                       __float2bfloat16(v.y - __bfloat162float(h1)));
    *reinterpret_cast<__nv_bfloat162*>(Kl + o + 2) =
        __nv_bfloat162(__float2bfloat16(v.z - __bfloat162float(h2)),
                       __float2bfloat16(v.w - __bfloat162float(h3)));
}

// ---------------- build V^T per head (transpose + split) ----------------
__global__ void build_vt(const float* __restrict__ kv,
                         __nv_bfloat16* __restrict__ Vth, __nv_bfloat16* __restrict__ Vtl)
{
    __shared__ float t[32][33];
    const int j0 = blockIdx.x * 32, d0 = blockIdx.y * 32, h = blockIdx.z;
    const int tx = threadIdx.x, ty = threadIdx.y;
#pragma unroll
    for (int i = 0; i < 4; i++)
        t[ty + i * 8][tx] = kv[(size_t)(j0 + ty + i * 8) * KVD + h * 256 + 128 + d0 + tx];
    __syncthreads();
    const size_t base = (size_t)h * DV * S_LEN;
#pragma unroll
    for (int i = 0; i < 4; i++) {
        const int d = d0 + ty + i * 8;
        const int j = j0 + tx;
        const float v = t[tx][ty + i * 8];
        const __nv_bfloat16 hh = __float2bfloat16(v);
        Vth[base + (size_t)d * S_LEN + j] = hh;
        Vtl[base + (size_t)d * S_LEN + j] = __float2bfloat16(v - __bfloat162float(hh));
    }
}

// ---------------- softmax: unnormalized exp -> ph/pl bf16, inv_sum per row -------
__global__ void softmax_split(const float* __restrict__ attn,
                              __nv_bfloat16* __restrict__ Ph, __nv_bfloat16* __restrict__ Pl,
                              float* __restrict__ inv_sum)
{
    const int i = blockIdx.x, h = blockIdx.y;
    const size_t base = (((size_t)h) << 20) + (size_t)i * S_LEN;
    const int len = i + 1;
    const int kend = ((i >> 7) + 1) * 128;
    __shared__ float red[256];

    float m = -3.4e38f;
    for (int j = threadIdx.x; j < len; j += 256) m = fmaxf(m, attn[base + j]);
    red[threadIdx.x] = m;
    __syncthreads();
    for (int o = 128; o > 0; o >>= 1) {
        if (threadIdx.x < o) red[threadIdx.x] = fmaxf(red[threadIdx.x], red[threadIdx.x + o]);
        __syncthreads();
    }
    m = red[0];
    __syncthreads();

    float s = 0.0f;
    for (int j = threadIdx.x; j < len; j += 256) {
        const float p = __expf(attn[base + j] - m);
        s += p;
        const __nv_bfloat16 hh = __float2bfloat16(p);
        Ph[base + j] = hh;
        Pl[base + j] = __float2bfloat16(p - __bfloat162float(hh));
    }
    for (int j = len + threadIdx.x; j < kend; j += 256) {
        Ph[base + j] = __float2bfloat16(0.0f);
        Pl[base + j] = __float2bfloat16(0.0f);
    }
    red[threadIdx.x] = s;
    __syncthreads();
    for (int o = 128; o > 0; o >>= 1) {
        if (threadIdx.x < o) red[threadIdx.x] += red[threadIdx.x + o];
        __syncthreads();
    }
    if (threadIdx.x == 0) inv_sum[h * S_LEN + i] = 1.0f / red[0];
}

// ---------------- launch ----------------
extern "C" void kernel_launch(void* const* d_in, const int* in_sizes, int n_in,
                              void* d_out, int out_size)
{
    const float* hs       = (const float*)d_in[0];
    const float* w_kv_a   = (const float*)d_in[1];
    const float* q_gamma  = (const float*)d_in[2];
    const float* kv_gamma = (const float*)d_in[3];
    const float* w_q_b    = (const float*)d_in[4];
    const float* w_kv_b   = (const float*)d_in[5];
    const float* w_o      = (const float*)d_in[6];
    float* out = (float*)d_out;

    float *comp, *q, *kv, *kpe, *attn, *inv;
    __nv_bfloat16 *ah, *al, *wh, *wl, *qh, *ql, *kh, *kl, *vth, *vtl, *ph, *pl;
    cudaGetSymbolAddress((void**)&comp, g_comp);
    cudaGetSymbolAddress((void**)&ah,   g_ah);
    cudaGetSymbolAddress((void**)&al,   g_al);
    cudaGetSymbolAddress((void**)&wh,   g_wh);
    cudaGetSymbolAddress((void**)&wl,   g_wl);
    cudaGetSymbolAddress((void**)&q,    g_q);
    cudaGetSymbolAddress((void**)&kv,   g_kv);
    cudaGetSymbolAddress((void**)&kpe,  g_kpe);
    cudaGetSymbolAddress((void**)&attn, g_attn);
    cudaGetSymbolAddress((void**)&qh,   g_qh);
    cudaGetSymbolAddress((void**)&ql,   g_ql);
    cudaGetSymbolAddress((void**)&kh,   g_kh);
    cudaGetSymbolAddress((void**)&kl,   g_kl);
    cudaGetSymbolAddress((void**)&vth,  g_vth);
    cudaGetSymbolAddress((void**)&vtl,  g_vtl);
    cudaGetSymbolAddress((void**)&ph,   g_ph);
    cudaGetSymbolAddress((void**)&pl,   g_pl);
    cudaGetSymbolAddress((void**)&inv,  g_inv);

    const int GSM = 131072;
    cudaFuncSetAttribute(mma_gemm, cudaFuncAttributeMaxDynamicSharedMemorySize, GSM);
    cudaFuncSetAttribute(score_mma, cudaFuncAttributeMaxDynamicSharedMemorySize, GSM);
    cudaFuncSetAttribute(av_mma, cudaFuncAttributeMaxDynamicSharedMemorySize, GSM);
    const dim3 T256(256);
    const dim3 TW(32, 8);

    // 1) comp = hs @ w_kv_a  (M=1024, N=2112 (pad 2176), K=7168)
    conv_a<<<(S_LEN * HID_D / 4 + 255) / 256, 256>>>(hs, ah, al, S_LEN * HID_D / 4);
    conv_w<<<dim3(HID_D / 32, 2176 / 32), TW>>>(w_kv_a, wh, wl, HID_D, COMP_D);
    mma_gemm<<<dim3(17, 8), T256, GSM>>>(ah, al, wh, wl, comp, COMP_D, HID_D);

    // 2) k_pe RoPE
    rope_k_kernel<<<(S_LEN * 32) / 256, 256>>>(comp, kpe);

    // 3) q = rmsnorm(q_c) @ w_q_b  (M=1024, N=24576, K=1536)
    rmsnorm_bf16<<<S_LEN, 256>>>(comp, q_gamma, ah, al, QLORA, COMP_D);
    conv_w<<<dim3(QLORA / 32, QD / 32), TW>>>(w_q_b, wh, wl, QLORA, QD);
    mma_gemm<<<dim3(QD / 128, 8), T256, GSM>>>(ah, al, wh, wl, q, QD, QLORA);

    // 4) kv = rmsnorm(kv_c) @ w_kv_b  (M=1024, N=32768, K=512)
    rmsnorm_bf16<<<S_LEN, 256>>>(comp + QLORA, kv_gamma, ah, al, KVLORA, COMP_D);
    conv_w<<<dim3(KVLORA / 32, KVD / 32), TW>>>(w_kv_b, wh, wl, KVLORA, KVD);
    mma_gemm<<<dim3(KVD / 128, 8), T256, GSM>>>(ah, al, wh, wl, kv, KVD, KVLORA);

    // 5) attention staging (gather/transposes + RoPE(q) + splits)
    build_q<<<(NH * S_LEN * 48 + 255) / 256, 256>>>(q, qh, ql);
    build_k<<<(NH * S_LEN * 48 + 255) / 256, 256>>>(kv, kpe, kh, kl);
    build_vt<<<dim3(32, 4, NH), TW>>>(kv, vth, vtl);

    // 6) scores (tensor, causal tile skip) -> softmax -> AV (tensor)
    score_mma<<<dim3(8, 8, NH), T256, GSM>>>(qh, ql, kh, kl, attn);
    softmax_split<<<dim3(S_LEN, NH), 256>>>(attn, ph, pl, inv);
    av_mma<<<dim3(1, 8, NH), T256, GSM>>>(ph, pl, vth, vtl, inv, ah, al);

    // 7) out = ctx @ w_o  (M=1024, N=7168, K=16384)
    conv_w<<<dim3(CTX_D / 32, HID_D / 32), TW>>>(w_o, wh, wl, CTX_D, HID_D);
    mma_gemm<<<dim3(HID_D / 128, 8), T256, GSM>>>(ah, al, wh, wl, out, HID_D, CTX_D);
}

// round 5
// speedup vs baseline: 4.6576x; 1.2762x over previous
#include <cuda_runtime.h>
#include <cuda_fp16.h>
#include <math.h>
#include <stdint.h>

// ---------------- problem constants ----------------
#define S_LEN 1024
#define HID_D 7168
#define NH 128
#define DN 128
#define DR 64
#define DV 128
#define QLORA 1536
#define KVLORA 512
#define COMP_D (QLORA + KVLORA + DR)      // 2112
#define QD (NH * (DN + DR))               // 24576
#define KVD (NH * (DN + DV))              // 32768
#define CTX_D (NH * DV)                   // 16384
#define DQK 192

// ---------------- scratch (device globals) ----------------
__device__ float g_comp[S_LEN * COMP_D];
__device__ __half g_ah[(size_t)S_LEN * 16384];                   // activations hi
__device__ __half g_al[(size_t)S_LEN * 16384];                   // activations lo
__device__ __half g_wh[117440512];                               // weights (single fp16, transposed)
__device__ float g_q[(size_t)S_LEN * QD];
__device__ float g_kv[(size_t)S_LEN * KVD];
__device__ float g_kpe[S_LEN * DR];
__device__ float g_attn[(size_t)NH * S_LEN * S_LEN];
// attention staging (fp16 hi/lo, 3-pass precision)
__device__ __half g_qh[(size_t)NH * S_LEN * DQK];
__device__ __half g_ql[(size_t)NH * S_LEN * DQK];
__device__ __half g_kh[(size_t)NH * S_LEN * DQK];
__device__ __half g_kl[(size_t)NH * S_LEN * DQK];
__device__ __half g_vth[(size_t)NH * DV * S_LEN];
__device__ __half g_vtl[(size_t)NH * DV * S_LEN];
__device__ __half g_ph[(size_t)NH * S_LEN * S_LEN];
__device__ __half g_pl[(size_t)NH * S_LEN * S_LEN];
__device__ float g_inv[NH * S_LEN];

// ---------------- PTX helpers (base sm_103 ISA only) ----------------
__device__ __forceinline__ uint32_t smem_u32(const void* p) {
    uint32_t a;
    asm("{ .reg .u64 t; cvta.to.shared.u64 t, %1; cvt.u32.u64 %0, t; }" : "=r"(a) : "l"(p));
    return a;
}
#define CP16(dst, src) \
    asm volatile("cp.async.cg.shared.global [%0], [%1], 16;" :: "r"(dst), "l"(src) : "memory")
#define CP_COMMIT() asm volatile("cp.async.commit_group;" ::: "memory")
#define CP_WAIT1() asm volatile("cp.async.wait_group 1;" ::: "memory")
#define CP_WAIT0() asm volatile("cp.async.wait_group 0;" ::: "memory")

#define LDSM4(r, a) \
    asm volatile("ldmatrix.sync.aligned.m8n8.x4.shared.b16 {%0,%1,%2,%3}, [%4];" \
        : "=r"((r)[0]), "=r"((r)[1]), "=r"((r)[2]), "=r"((r)[3]) : "r"(a))

#define MMA_F16(d, a, b0, b1) \
    asm volatile("mma.sync.aligned.m16n8k16.row.col.f32.f16.f16.f32 " \
        "{%0,%1,%2,%3}, {%4,%5,%6,%7}, {%8,%9}, {%0,%1,%2,%3};" \
        : "+f"((d)[0]), "+f"((d)[1]), "+f"((d)[2]), "+f"((d)[3]) \
        : "r"((a)[0]), "r"((a)[1]), "r"((a)[2]), "r"((a)[3]), "r"(b0), "r"(b1))

#define SWZ(o) ((o) ^ (((o) >> 3) & 0x70))

__device__ __forceinline__ void split_h(float v, __half& h, __half& l) {
    h = __float2half_rn(v);
    l = __float2half_rn(v - __half2float(h));
}

// ---------------- shared GEMM body ----------------
// NPASS=2: C += (Ah+Al) @ Bh^T         (weight path, b single fp16)
// NPASS=3: C += (Ah+Al) @ (Bh+Bl)^T    (attention path, drop al*bl)
// A rows at (m0+row)*K, B rows at (n0+row)*K. nch chunks of 64.
template <int NPASS>
__device__ __forceinline__ void gemm_body(
    const __half* __restrict__ Ah, const __half* __restrict__ Al,
    const __half* __restrict__ Bh, const __half* __restrict__ Bl,
    int K, int nch, int m0, int n0, uint32_t sb, int tid, float acc[2][8][4])
{
    constexpr int NT = NPASS + 1;          // smem tensors per stage
    constexpr int STAGE = NT * 16384;
    const int lane = tid & 31;
    const int wid = tid >> 5;
    const int wm = (wid & 3) * 32;
    const int wn = (wid >> 2) * 64;

    auto load_stage = [&](int c, int s) {
        const int kc = c << 6;
#pragma unroll
        for (int it = 0; it < NT * 4; it++) {
            const int t = tid + it * 256;
            const int tensor = t >> 10;
            const int rem = t & 1023;
            const int row = rem >> 3;
            const int ch = rem & 7;
            const __half* src;
            int grow;
            if (tensor == 0)      { src = Ah; grow = m0 + row; }
            else if (tensor == 1) { src = Al; grow = m0 + row; }
            else if (tensor == 2) { src = Bh; grow = n0 + row; }
            else                  { src = Bl; grow = n0 + row; }
            const __half* sp = src + (size_t)grow * K + kc + ch * 8;
            const uint32_t dst = sb + s * STAGE + tensor * 16384 + SWZ(row * 128 + ch * 16);
            CP16(dst, sp);
        }
        CP_COMMIT();
    };

    load_stage(0, 0);

    for (int c = 0; c < nch; c++) {
        const int buf = c & 1;
        if (c + 1 < nch) { load_stage(c + 1, buf ^ 1); CP_WAIT1(); }
        else             { CP_WAIT0(); }
        __syncthreads();

        const uint32_t st = sb + buf * STAGE;
        const uint32_t sA_h = st;
        const uint32_t sA_l = st + 16384;
        const uint32_t sB_h = st + 32768;
        const uint32_t sB_l = st + 49152;
        const int rl = lane & 15;
        const int kb = lane >> 4;

#pragma unroll
        for (int k16 = 0; k16 < 4; k16++) {
            const int kbyte = k16 * 32 + kb * 16;
            uint32_t afh[2][4], afl[2][4], bfh[4][4], bfl[4][4];
#pragma unroll
            for (int mt = 0; mt < 2; mt++) {
                const uint32_t off = SWZ((wm + mt * 16 + rl) * 128 + kbyte);
                LDSM4(afh[mt], sA_h + off);
                LDSM4(afl[mt], sA_l + off);
            }
#pragma unroll
            for (int q = 0; q < 4; q++) {
                const uint32_t off = SWZ((wn + q * 16 + rl) * 128 + kbyte);
                LDSM4(bfh[q], sB_h + off);
                if (NPASS == 3) LDSM4(bfl[q], sB_l + off);
            }
#pragma unroll
            for (int mt = 0; mt < 2; mt++)
#pragma unroll
                for (int nt = 0; nt < 8; nt++) {
                    const int q = nt >> 1, s = nt & 1;
                    MMA_F16(acc[mt][nt], afh[mt], bfh[q][s], bfh[q][s + 2]);
                    MMA_F16(acc[mt][nt], afl[mt], bfh[q][s], bfh[q][s + 2]);
                    if (NPASS == 3)
                        MMA_F16(acc[mt][nt], afh[mt], bfl[q][s], bfl[q][s + 2]);
                }
        }
        __syncthreads();
    }
}

// ---------------- dense GEMM: C = (Ah+Al) @ Bh^T, 2-pass ----------------
__global__ __launch_bounds__(256, 1) void mma_gemm(
    const __half* __restrict__ Ah, const __half* __restrict__ Al,
    const __half* __restrict__ Bh,
    float* __restrict__ C, int N, int K)
{
    extern __shared__ __align__(128) char smem[];
    const uint32_t sb = smem_u32(smem);
    const int tid = threadIdx.x;
    const int lane = tid & 31;
    const int wid = tid >> 5;
    const int m0 = blockIdx.y * 128, n0 = blockIdx.x * 128;
    const int wm = (wid & 3) * 32, wn = (wid >> 2) * 64;

    float acc[2][8][4];
#pragma unroll
    for (int mt = 0; mt < 2; mt++)
#pragma unroll
        for (int nt = 0; nt < 8; nt++)
#pragma unroll
            for (int e = 0; e < 4; e++) acc[mt][nt][e] = 0.0f;

    gemm_body<2>(Ah, Al, Bh, nullptr, K, K >> 6, m0, n0, sb, tid, acc);

#pragma unroll
    for (int mt = 0; mt < 2; mt++) {
        const int row = m0 + wm + mt * 16 + (lane >> 2);
#pragma unroll
        for (int nt = 0; nt < 8; nt++) {
            const int col = n0 + wn + nt * 8 + (lane & 3) * 2;
            if (col < N) {
                *reinterpret_cast<float2*>(C + (size_t)row * N + col) =
                    make_float2(acc[mt][nt][0], acc[mt][nt][1]);
                *reinterpret_cast<float2*>(C + (size_t)(row + 8) * N + col) =
                    make_float2(acc[mt][nt][2], acc[mt][nt][3]);
            }
        }
    }
}

// ---------------- score GEMM: attn[h] = scale * Q[h] @ K[h]^T (3-pass) ----------
__global__ __launch_bounds__(256, 1) void score_mma(
    const __half* __restrict__ Qh, const __half* __restrict__ Ql,
    const __half* __restrict__ Kh, const __half* __restrict__ Kl,
    float* __restrict__ attn)
{
    const int jt = blockIdx.x, it = blockIdx.y, h = blockIdx.z;
    if (jt > it) return;
    extern __shared__ __align__(128) char smem[];
    const uint32_t sb = smem_u32(smem);
    const int tid = threadIdx.x;
    const int lane = tid & 31;
    const int wid = tid >> 5;
    const int m0 = it * 128, n0 = jt * 128;
    const int wm = (wid & 3) * 32, wn = (wid >> 2) * 64;
    const size_t hoff = (size_t)h * S_LEN * DQK;

    float acc[2][8][4];
#pragma unroll
    for (int mt = 0; mt < 2; mt++)
#pragma unroll
        for (int nt = 0; nt < 8; nt++)
#pragma unroll
            for (int e = 0; e < 4; e++) acc[mt][nt][e] = 0.0f;

    gemm_body<3>(Qh + hoff, Ql + hoff, Kh + hoff, Kl + hoff, DQK, 3, m0, n0, sb, tid, acc);

    const float scale = 0.07216878364870323f;   // 1/sqrt(192)
    float* C = attn + (((size_t)h) << 20);
#pragma unroll
    for (int mt = 0; mt < 2; mt++) {
        const int row = m0 + wm + mt * 16 + (lane >> 2);
#pragma unroll
        for (int nt = 0; nt < 8; nt++) {
            const int col = n0 + wn + nt * 8 + (lane & 3) * 2;
            *reinterpret_cast<float2*>(C + (size_t)row * S_LEN + col) =
                make_float2(acc[mt][nt][0] * scale, acc[mt][nt][1] * scale);
            *reinterpret_cast<float2*>(C + (size_t)(row + 8) * S_LEN + col) =
                make_float2(acc[mt][nt][2] * scale, acc[mt][nt][3] * scale);
        }
    }
}

// ---------------- AV GEMM: ctx[h] = (P[h] @ Vt[h]^T) * inv_sum (3-pass) ----------
__global__ __launch_bounds__(256, 1) void av_mma(
    const __half* __restrict__ Ph, const __half* __restrict__ Pl,
    const __half* __restrict__ Vth, const __half* __restrict__ Vtl,
    const float* __restrict__ inv_sum,
    __half* __restrict__ ch, __half* __restrict__ cl)
{
    const int it = blockIdx.y, h = blockIdx.z;
    extern __shared__ __align__(128) char smem[];
    const uint32_t sb = smem_u32(smem);
    const int tid = threadIdx.x;
    const int lane = tid & 31;
    const int wid = tid >> 5;
    const int m0 = it * 128;
    const int wm = (wid & 3) * 32, wn = (wid >> 2) * 64;

    float acc[2][8][4];
#pragma unroll
    for (int mt = 0; mt < 2; mt++)
#pragma unroll
        for (int nt = 0; nt < 8; nt++)
#pragma unroll
            for (int e = 0; e < 4; e++) acc[mt][nt][e] = 0.0f;

    const size_t poff = ((size_t)h) << 20;
    const size_t voff = (size_t)h * DV * S_LEN;
    gemm_body<3>(Ph + poff, Pl + poff, Vth + voff, Vtl + voff,
                 S_LEN, (it + 1) * 2, m0, 0, sb, tid, acc);

#pragma unroll
    for (int mt = 0; mt < 2; mt++) {
#pragma unroll
        for (int half_i = 0; half_i < 2; half_i++) {
            const int row = m0 + wm + mt * 16 + (lane >> 2) + half_i * 8;
            const float inv = inv_sum[h * S_LEN + row];
#pragma unroll
            for (int nt = 0; nt < 8; nt++) {
                const int col = wn + nt * 8 + (lane & 3) * 2;
                const size_t o = (size_t)row * CTX_D + (size_t)h * DV + col;
                const float v0 = acc[mt][nt][half_i * 2] * inv;
                const float v1 = acc[mt][nt][half_i * 2 + 1] * inv;
                __half h0, l0, h1, l1;
                split_h(v0, h0, l0);
                split_h(v1, h1, l1);
                *reinterpret_cast<__half2*>(ch + o) = __half2(h0, h1);
                *reinterpret_cast<__half2*>(cl + o) = __half2(l0, l1);
            }
        }
    }
}

// ---------------- weight convert + transpose: W[K,N] fp32 -> T[Npad,K] fp16 ------
__global__ void conv_w(const float* __restrict__ W, __half* __restrict__ Th, int K, int N)
{
    __shared__ float t[32][33];
    const int k0 = blockIdx.x * 32, n0 = blockIdx.y * 32;
    const int tx = threadIdx.x, ty = threadIdx.y;
#pragma unroll
    for (int i = 0; i < 4; i++) {
        const int k = k0 + ty + i * 8;
        const int n = n0 + tx;
        t[ty + i * 8][tx] = (n < N) ? W[(size_t)k * N + n] : 0.0f;
    }
    __syncthreads();
#pragma unroll
    for (int i = 0; i < 4; i++) {
        const int n = n0 + ty + i * 8;
        const int k = k0 + tx;
        Th[(size_t)n * K + k] = __float2half_rn(t[tx][ty + i * 8]);
    }
}

// ---------------- activation convert (fp32 -> fp16 hi/lo) ----------------
__global__ void conv_a(const float* __restrict__ A, __half* __restrict__ H,
                       __half* __restrict__ L, int n4)
{
    const int i = blockIdx.x * blockDim.x + threadIdx.x;
    if (i >= n4) return;
    const float4 v = reinterpret_cast<const float4*>(A)[i];
    __half h0, l0, h1, l1, h2, l2, h3, l3;
    split_h(v.x, h0, l0); split_h(v.y, h1, l1);
    split_h(v.z, h2, l2); split_h(v.w, h3, l3);
    __half2* Hp = reinterpret_cast<__half2*>(H) + i * 2;
    __half2* Lp = reinterpret_cast<__half2*>(L) + i * 2;
    Hp[0] = __half2(h0, h1); Hp[1] = __half2(h2, h3);
    Lp[0] = __half2(l0, l1); Lp[1] = __half2(l2, l3);
}

// ---------------- rmsnorm fused to fp16 hi/lo ----------------
__global__ void rmsnorm_h(const float* __restrict__ x, const float* __restrict__ gamma,
                          __half* __restrict__ yh, __half* __restrict__ yl,
                          int D, int xstride)
{
    const int row = blockIdx.x;
    const float* xr = x + (size_t)row * xstride;
    float s = 0.0f;
    for (int i = threadIdx.x; i < D; i += 256) { const float v = xr[i]; s += v * v; }
    __shared__ float red[256];
    red[threadIdx.x] = s;
    __syncthreads();
    for (int o = 128; o > 0; o >>= 1) {
        if (threadIdx.x < o) red[threadIdx.x] += red[threadIdx.x + o];
        __syncthreads();
    }
    const float inv = rsqrtf(red[0] / (float)D + 1e-6f);
    for (int i = threadIdx.x; i < D; i += 256) {
        const float v = xr[i] * inv * gamma[i];
        __half h, l;
        split_h(v, h, l);
        yh[(size_t)row * D + i] = h;
        yl[(size_t)row * D + i] = l;
    }
}

// ---------------- RoPE helpers ----------------
__device__ __forceinline__ void rope_cs(int s, int d, float& c, float& sn)
{
    const float inv = exp2f(-(float)d * (13.287712379549449f / 32.0f));
    sincosf((float)s * inv, &sn, &c);
}

__global__ void rope_k_kernel(const float* __restrict__ comp, float* __restrict__ kpe)
{
    const int t = blockIdx.x * blockDim.x + threadIdx.x;
    if (t >= S_LEN * 32) return;
    const int d = t & 31;
    const int s = t >> 5;
    float c, sn;
    rope_cs(s, d, c, sn);
    const float* src = comp + (size_t)s * COMP_D + QLORA + KVLORA;
    const float x1 = src[d], x2 = src[d + 32];
    kpe[s * DR + d]      = x1 * c - x2 * sn;
    kpe[s * DR + d + 32] = x2 * c + x1 * sn;
}

// ---------------- build Q per head (gather + RoPE + split) ----------------
__global__ void build_q(const float* __restrict__ q,
                        __half* __restrict__ Qh, __half* __restrict__ Ql)
{
    const int t = blockIdx.x * blockDim.x + threadIdx.x;
    if (t >= NH * S_LEN * 48) return;
    const int c4 = t % 48;
    const int i  = (t / 48) & (S_LEN - 1);
    const int h  = t / (48 * S_LEN);

    const float* src = q + (size_t)i * QD + h * DQK;
    float4 v;
    if (c4 < 32) {
        v = *reinterpret_cast<const float4*>(src + c4 * 4);
    } else {
        const int d0 = (c4 - 32) * 4;
        const float4 a = *reinterpret_cast<const float4*>(src + DN + d0);
        const float4 b = *reinterpret_cast<const float4*>(src + DN + (d0 ^ 32));
        const float* ap = &a.x;
        const float* bp = &b.x;
        float* vp = &v.x;
#pragma unroll
        for (int e = 0; e < 4; e++) {
            const int d = d0 + e;
            float c, sn;
            rope_cs(i, d & 31, c, sn);
            vp[e] = (d < 32) ? (ap[e] * c - bp[e] * sn)
                             : (ap[e] * c + bp[e] * sn);
        }
    }
    const size_t o = ((size_t)h * S_LEN + i) * DQK + c4 * 4;
    __half h0, l0, h1, l1, h2, l2, h3, l3;
    split_h(v.x, h0, l0); split_h(v.y, h1, l1);
    split_h(v.z, h2, l2); split_h(v.w, h3, l3);
    *reinterpret_cast<__half2*>(Qh + o)     = __half2(h0, h1);
    *reinterpret_cast<__half2*>(Qh + o + 2) = __half2(h2, h3);
    *reinterpret_cast<__half2*>(Ql + o)     = __half2(l0, l1);
    *reinterpret_cast<__half2*>(Ql + o + 2) = __half2(l2, l3);
}

// ---------------- build K per head ----------------
__global__ void build_k(const float* __restrict__ kv, const float* __restrict__ kpe,
                        __half* __restrict__ Kh, __half* __restrict__ Kl)
{
    const int t = blockIdx.x * blockDim.x + threadIdx.x;
    if (t >= NH * S_LEN * 48) return;
    const int c4 = t % 48;
    const int j  = (t / 48) & (S_LEN - 1);
    const int h  = t / (48 * S_LEN);

    float4 v;
    if (c4 < 32) v = *reinterpret_cast<const float4*>(kv + (size_t)j * KVD + h * 256 + c4 * 4);
    else         v = *reinterpret_cast<const float4*>(kpe + j * DR + (c4 - 32) * 4);

    const size_t o = ((size_t)h * S_LEN + j) * DQK + c4 * 4;
    __half h0, l0, h1, l1, h2, l2, h3, l3;
    split_h(v.x, h0, l0); split_h(v.y, h1, l1);
    split_h(v.z, h2, l2); split_h(v.w, h3, l3);
    *reinterpret_cast<__half2*>(Kh + o)     = __half2(h0, h1);
    *reinterpret_cast<__half2*>(Kh + o + 2) = __half2(h2, h3);
    *reinterpret_cast<__half2*>(Kl + o)     = __half2(l0, l1);
    *reinterpret_cast<__half2*>(Kl + o + 2) = __half2(l2, l3);
}

// ---------------- build V^T per head (transpose + split) ----------------
__global__ void build_vt(const float* __restrict__ kv,
                         __half* __restrict__ Vth, __half* __restrict__ Vtl)
{
    __shared__ float t[32][33];
    const int j0 = blockIdx.x * 32, d0 = blockIdx.y * 32, h = blockIdx.z;
    const int tx = threadIdx.x, ty = threadIdx.y;
#pragma unroll
    for (int i = 0; i < 4; i++)
        t[ty + i * 8][tx] = kv[(size_t)(j0 + ty + i * 8) * KVD + h * 256 + 128 + d0 + tx];
    __syncthreads();
    const size_t base = (size_t)h * DV * S_LEN;
#pragma unroll
    for (int i = 0; i < 4; i++) {
        const int d = d0 + ty + i * 8;
        const int j = j0 + tx;
        __half hh, ll;
        split_h(t[tx][ty + i * 8], hh, ll);
        Vth[base + (size_t)d * S_LEN + j] = hh;
        Vtl[base + (size_t)d * S_LEN + j] = ll;
    }
}

// ---------------- softmax: unnormalized exp -> ph/pl fp16, inv_sum per row -------
__global__ void softmax_split(const float* __restrict__ attn,
                              __half* __restrict__ Ph, __half* __restrict__ Pl,
                              float* __restrict__ inv_sum)
{
    const int i = blockIdx.x, h = blockIdx.y;
    const size_t base = (((size_t)h) << 20) + (size_t)i * S_LEN;
    const int len = i + 1;
    const int kend = ((i >> 7) + 1) * 128;
    __shared__ float red[256];

    float m = -3.4e38f;
    for (int j = threadIdx.x; j < len; j += 256) m = fmaxf(m, attn[base + j]);
    red[threadIdx.x] = m;
    __syncthreads();
    for (int o = 128; o > 0; o >>= 1) {
        if (threadIdx.x < o) red[threadIdx.x] = fmaxf(red[threadIdx.x], red[threadIdx.x + o]);
        __syncthreads();
    }
    m = red[0];
    __syncthreads();

    float s = 0.0f;
    for (int j = threadIdx.x; j < len; j += 256) {
        const float p = __expf(attn[base + j] - m);
        s += p;
        __half hh, ll;
        split_h(p, hh, ll);
        Ph[base + j] = hh;
        Pl[base + j] = ll;
    }
    for (int j = len + threadIdx.x; j < kend; j += 256) {
        Ph[base + j] = __float2half_rn(0.0f);
        Pl[base + j] = __float2half_rn(0.0f);
    }
    red[threadIdx.x] = s;
    __syncthreads();
    for (int o = 128; o > 0; o >>= 1) {
        if (threadIdx.x < o) red[threadIdx.x] += red[threadIdx.x + o];
        __syncthreads();
    }
    if (threadIdx.x == 0) inv_sum[h * S_LEN + i] = 1.0f / red[0];
}

// ---------------- launch ----------------
extern "C" void kernel_launch(void* const* d_in, const int* in_sizes, int n_in,
                              void* d_out, int out_size)
{
    const float* hs       = (const float*)d_in[0];
    const float* w_kv_a   = (const float*)d_in[1];
    const float* q_gamma  = (const float*)d_in[2];
    const float* kv_gamma = (const float*)d_in[3];
    const float* w_q_b    = (const float*)d_in[4];
    const float* w_kv_b   = (const float*)d_in[5];
    const float* w_o      = (const float*)d_in[6];
    float* out = (float*)d_out;

    float *comp, *q, *kv, *kpe, *attn, *inv;
    __half *ah, *al, *wh, *qh, *ql, *kh, *kl, *vth, *vtl, *ph, *pl;
    cudaGetSymbolAddress((void**)&comp, g_comp);
    cudaGetSymbolAddress((void**)&ah,   g_ah);
    cudaGetSymbolAddress((void**)&al,   g_al);
    cudaGetSymbolAddress((void**)&wh,   g_wh);
    cudaGetSymbolAddress((void**)&q,    g_q);
    cudaGetSymbolAddress((void**)&kv,   g_kv);
    cudaGetSymbolAddress((void**)&kpe,  g_kpe);
    cudaGetSymbolAddress((void**)&attn, g_attn);
    cudaGetSymbolAddress((void**)&qh,   g_qh);
    cudaGetSymbolAddress((void**)&ql,   g_ql);
    cudaGetSymbolAddress((void**)&kh,   g_kh);
    cudaGetSymbolAddress((void**)&kl,   g_kl);
    cudaGetSymbolAddress((void**)&vth,  g_vth);
    cudaGetSymbolAddress((void**)&vtl,  g_vtl);
    cudaGetSymbolAddress((void**)&ph,   g_ph);
    cudaGetSymbolAddress((void**)&pl,   g_pl);
    cudaGetSymbolAddress((void**)&inv,  g_inv);

    cudaFuncSetAttribute(mma_gemm, cudaFuncAttributeMaxDynamicSharedMemorySize, 98304);
    cudaFuncSetAttribute(score_mma, cudaFuncAttributeMaxDynamicSharedMemorySize, 131072);
    cudaFuncSetAttribute(av_mma, cudaFuncAttributeMaxDynamicSharedMemorySize, 131072);
    const dim3 T256(256);
    const dim3 TW(32, 8);

    // 1) comp = hs @ w_kv_a  (M=1024, N=2112 (pad 2176), K=7168)
    conv_a<<<(S_LEN * HID_D / 4 + 255) / 256, 256>>>(hs, ah, al, S_LEN * HID_D / 4);
    conv_w<<<dim3(HID_D / 32, 2176 / 32), TW>>>(w_kv_a, wh, HID_D, COMP_D);
    mma_gemm<<<dim3(17, 8), T256, 98304>>>(ah, al, wh, comp, COMP_D, HID_D);

    // 2) k_pe RoPE
    rope_k_kernel<<<(S_LEN * 32) / 256, 256>>>(comp, kpe);

    // 3) q = rmsnorm(q_c) @ w_q_b  (M=1024, N=24576, K=1536)
    rmsnorm_h<<<S_LEN, 256>>>(comp, q_gamma, ah, al, QLORA, COMP_D);
    conv_w<<<dim3(QLORA / 32, QD / 32), TW>>>(w_q_b, wh, QLORA, QD);
    mma_gemm<<<dim3(QD / 128, 8), T256, 98304>>>(ah, al, wh, q, QD, QLORA);

    // 4) kv = rmsnorm(kv_c) @ w_kv_b  (M=1024, N=32768, K=512)
    rmsnorm_h<<<S_LEN, 256>>>(comp + QLORA, kv_gamma, ah, al, KVLORA, COMP_D);
    conv_w<<<dim3(KVLORA / 32, KVD / 32), TW>>>(w_kv_b, wh, KVLORA, KVD);
    mma_gemm<<<dim3(KVD / 128, 8), T256, 98304>>>(ah, al, wh, kv, KVD, KVLORA);

    // 5) attention staging
    build_q<<<(NH * S_LEN * 48 + 255) / 256, 256>>>(q, qh, ql);
    build_k<<<(NH * S_LEN * 48 + 255) / 256, 256>>>(kv, kpe, kh, kl);
    build_vt<<<dim3(32, 4, NH), TW>>>(kv, vth, vtl);

    // 6) scores (tensor, causal skip) -> softmax -> AV (tensor)
    score_mma<<<dim3(8, 8, NH), T256, 131072>>>(qh, ql, kh, kl, attn);
    softmax_split<<<dim3(S_LEN, NH), 256>>>(attn, ph, pl, inv);
    av_mma<<<dim3(1, 8, NH), T256, 131072>>>(ph, pl, vth, vtl, inv, ah, al);

    // 7) out = ctx @ w_o  (M=1024, N=7168, K=16384)
    conv_w<<<dim3(CTX_D / 32, HID_D / 32), TW>>>(w_o, wh, CTX_D, HID_D);
    mma_gemm<<<dim3(HID_D / 128, 8), T256, 98304>>>(ah, al, wh, out, HID_D, CTX_D);
}

// round 6
// speedup vs baseline: 5.5304x; 1.1874x over previous
#include <cuda_runtime.h>
#include <cuda_fp16.h>
#include <math.h>
#include <stdint.h>

// ---------------- problem constants ----------------
#define S_LEN 1024
#define HID_D 7168
#define NH 128
#define DN 128
#define DR 64
#define DV 128
#define QLORA 1536
#define KVLORA 512
#define COMP_D (QLORA + KVLORA + DR)      // 2112
#define QD (NH * (DN + DR))               // 24576
#define KVD (NH * (DN + DV))              // 32768
#define CTX_D (NH * DV)                   // 16384
#define DQK 192

// ---------------- scratch (device globals) ----------------
__device__ float g_comp[S_LEN * COMP_D];
__device__ __half g_ah[(size_t)S_LEN * 16384];                   // activations hi (also ctx)
__device__ __half g_al[(size_t)S_LEN * 16384];                   // activations lo
__device__ __half g_wh[117440512];                               // weights hi (transposed)
__device__ __half g_wla[15597568];                               // w_kv_a lo (2176*7168)
__device__ float g_kv[(size_t)S_LEN * KVD];                      // v half only used
__device__ float g_kpe[S_LEN * DR];
__device__ float g_attn[(size_t)NH * S_LEN * S_LEN];
__device__ __half g_qh[(size_t)NH * S_LEN * DQK];
__device__ __half g_ql[(size_t)NH * S_LEN * DQK];
__device__ __half g_kh[(size_t)NH * S_LEN * DQK];
__device__ __half g_kl[(size_t)NH * S_LEN * DQK];
__device__ __half g_vth[(size_t)NH * DV * S_LEN];
__device__ __half g_vtl[(size_t)NH * DV * S_LEN];
__device__ __half g_ph[(size_t)NH * S_LEN * S_LEN];
__device__ __half g_pl[(size_t)NH * S_LEN * S_LEN];
__device__ float g_inv[NH * S_LEN];

// ---------------- PTX helpers ----------------
__device__ __forceinline__ uint32_t smem_u32(const void* p) {
    uint32_t a;
    asm("{ .reg .u64 t; cvta.to.shared.u64 t, %1; cvt.u32.u64 %0, t; }" : "=r"(a) : "l"(p));
    return a;
}
#define CP16(dst, src) \
    asm volatile("cp.async.cg.shared.global [%0], [%1], 16;" :: "r"(dst), "l"(src) : "memory")
#define CP_COMMIT() asm volatile("cp.async.commit_group;" ::: "memory")
#define CP_WAIT1() asm volatile("cp.async.wait_group 1;" ::: "memory")
#define CP_WAIT0() asm volatile("cp.async.wait_group 0;" ::: "memory")

#define LDSM4(r, a) \
    asm volatile("ldmatrix.sync.aligned.m8n8.x4.shared.b16 {%0,%1,%2,%3}, [%4];" \
        : "=r"((r)[0]), "=r"((r)[1]), "=r"((r)[2]), "=r"((r)[3]) : "r"(a))

#define MMA_F16(d, a, b0, b1) \
    asm volatile("mma.sync.aligned.m16n8k16.row.col.f32.f16.f16.f32 " \
        "{%0,%1,%2,%3}, {%4,%5,%6,%7}, {%8,%9}, {%0,%1,%2,%3};" \
        : "+f"((d)[0]), "+f"((d)[1]), "+f"((d)[2]), "+f"((d)[3]) \
        : "r"((a)[0]), "r"((a)[1]), "r"((a)[2]), "r"((a)[3]), "r"(b0), "r"(b1))

#define SWZ(o) ((o) ^ (((o) >> 3) & 0x70))

__device__ __forceinline__ void split_h(float v, __half& h, __half& l) {
    h = __float2half_rn(v);
    l = __float2half_rn(v - __half2float(h));
}

// ---------------- shared GEMM body ----------------
// NPASS=1: ah*bh        NPASS=2: ah*bh + al*bh        NPASS=3: + ah*bl
template <int NPASS>
__device__ __forceinline__ void gemm_body(
    const __half* __restrict__ Ah, const __half* __restrict__ Al,
    const __half* __restrict__ Bh, const __half* __restrict__ Bl,
    int K, int nch, int m0, int n0, uint32_t sb, int tid, float acc[2][8][4])
{
    constexpr int CA = (NPASS >= 2) ? 2 : 1;
    constexpr int CB = (NPASS == 3) ? 2 : 1;
    constexpr int NT = CA + CB;
    constexpr int STAGE = NT * 16384;
    const int lane = tid & 31;
    const int wid = tid >> 5;
    const int wm = (wid & 3) * 32;
    const int wn = (wid >> 2) * 64;

    auto load_stage = [&](int c, int s) {
        const int kc = c << 6;
#pragma unroll
        for (int it = 0; it < NT * 4; it++) {
            const int t = tid + it * 256;
            const int tensor = t >> 10;
            const int rem = t & 1023;
            const int row = rem >> 3;
            const int ch = rem & 7;
            const __half* src;
            int grow;
            if (tensor < CA) {
                src = (CA == 2 && tensor == 1) ? Al : Ah;
                grow = m0 + row;
            } else {
                src = (CB == 2 && tensor == CA + 1) ? Bl : Bh;
                grow = n0 + row;
            }
            const __half* sp = src + (size_t)grow * K + kc + ch * 8;
            const uint32_t dst = sb + s * STAGE + tensor * 16384 + SWZ(row * 128 + ch * 16);
            CP16(dst, sp);
        }
        CP_COMMIT();
    };

    load_stage(0, 0);

    for (int c = 0; c < nch; c++) {
        const int buf = c & 1;
        if (c + 1 < nch) { load_stage(c + 1, buf ^ 1); CP_WAIT1(); }
        else             { CP_WAIT0(); }
        __syncthreads();

        const uint32_t st = sb + buf * STAGE;
        const uint32_t sA_h = st;
        const uint32_t sA_l = st + 16384;
        const uint32_t sB_h = st + CA * 16384;
        const uint32_t sB_l = sB_h + 16384;
        const int rl = lane & 15;
        const int kb = lane >> 4;

#pragma unroll
        for (int k16 = 0; k16 < 4; k16++) {
            const int kbyte = k16 * 32 + kb * 16;
            uint32_t afh[2][4], afl[2][4], bfh[4][4], bfl[4][4];
#pragma unroll
            for (int mt = 0; mt < 2; mt++) {
                const uint32_t off = SWZ((wm + mt * 16 + rl) * 128 + kbyte);
                LDSM4(afh[mt], sA_h + off);
                if (CA == 2) LDSM4(afl[mt], sA_l + off);
            }
#pragma unroll
            for (int q = 0; q < 4; q++) {
                const uint32_t off = SWZ((wn + q * 16 + rl) * 128 + kbyte);
                LDSM4(bfh[q], sB_h + off);
                if (CB == 2) LDSM4(bfl[q], sB_l + off);
            }
#pragma unroll
            for (int mt = 0; mt < 2; mt++)
#pragma unroll
                for (int nt = 0; nt < 8; nt++) {
                    const int q = nt >> 1, s = nt & 1;
                    MMA_F16(acc[mt][nt], afh[mt], bfh[q][s], bfh[q][s + 2]);
                    if (CA == 2) MMA_F16(acc[mt][nt], afl[mt], bfh[q][s], bfh[q][s + 2]);
                    if (CB == 2) MMA_F16(acc[mt][nt], afh[mt], bfl[q][s], bfl[q][s + 2]);
                }
        }
        __syncthreads();
    }
}

#define GEMM_PROLOGUE() \
    extern __shared__ __align__(128) char smem[]; \
    const uint32_t sb = smem_u32(smem); \
    const int tid = threadIdx.x; \
    const int lane = tid & 31; \
    const int wid = tid >> 5; \
    const int m0 = blockIdx.y * 128, n0 = blockIdx.x * 128; \
    const int wm = (wid & 3) * 32, wn = (wid >> 2) * 64; \
    float acc[2][8][4]; \
    _Pragma("unroll") for (int mt = 0; mt < 2; mt++) \
    _Pragma("unroll") for (int nt = 0; nt < 8; nt++) \
    _Pragma("unroll") for (int e = 0; e < 4; e++) acc[mt][nt][e] = 0.0f;

// ---------------- comp GEMM: 3-pass, fp32 out ----------------
__global__ __launch_bounds__(256, 1) void mma_gemm3(
    const __half* __restrict__ Ah, const __half* __restrict__ Al,
    const __half* __restrict__ Bh, const __half* __restrict__ Bl,
    float* __restrict__ C, int N, int K)
{
    GEMM_PROLOGUE();
    gemm_body<3>(Ah, Al, Bh, Bl, K, K >> 6, m0, n0, sb, tid, acc);
#pragma unroll
    for (int mt = 0; mt < 2; mt++) {
        const int row = m0 + wm + mt * 16 + (lane >> 2);
#pragma unroll
        for (int nt = 0; nt < 8; nt++) {
            const int col = n0 + wn + nt * 8 + (lane & 3) * 2;
            if (col < N) {
                *reinterpret_cast<float2*>(C + (size_t)row * N + col) =
                    make_float2(acc[mt][nt][0], acc[mt][nt][1]);
                *reinterpret_cast<float2*>(C + (size_t)(row + 8) * N + col) =
                    make_float2(acc[mt][nt][2], acc[mt][nt][3]);
            }
        }
    }
}

// ---------------- w_o GEMM: 1-pass, fp32 out ----------------
__global__ __launch_bounds__(256, 1) void mma_gemm1(
    const __half* __restrict__ Ah, const __half* __restrict__ Bh,
    float* __restrict__ C, int N, int K)
{
    GEMM_PROLOGUE();
    gemm_body<1>(Ah, nullptr, Bh, nullptr, K, K >> 6, m0, n0, sb, tid, acc);
#pragma unroll
    for (int mt = 0; mt < 2; mt++) {
        const int row = m0 + wm + mt * 16 + (lane >> 2);
#pragma unroll
        for (int nt = 0; nt < 8; nt++) {
            const int col = n0 + wn + nt * 8 + (lane & 3) * 2;
            *reinterpret_cast<float2*>(C + (size_t)row * N + col) =
                make_float2(acc[mt][nt][0], acc[mt][nt][1]);
            *reinterpret_cast<float2*>(C + (size_t)(row + 8) * N + col) =
                make_float2(acc[mt][nt][2], acc[mt][nt][3]);
        }
    }
}

// ---------------- RoPE angle ----------------
__device__ __forceinline__ void rope_cs(int s, int d, float& c, float& sn)
{
    const float inv = exp2f(-(float)d * (13.287712379549449f / 32.0f));
    sincosf((float)s * inv, &sn, &c);
}

// ---------------- q GEMM: 2-pass, fused RoPE + split, per-head layout -----------
// N = 24576; writes Qh/Ql [h][row][192]
__global__ __launch_bounds__(256, 1) void mma_gemm_q(
    const __half* __restrict__ Ah, const __half* __restrict__ Al,
    const __half* __restrict__ Bh,
    __half* __restrict__ Qh, __half* __restrict__ Ql)
{
    GEMM_PROLOGUE();
    gemm_body<2>(Ah, Al, Bh, nullptr, QLORA, QLORA >> 6, m0, n0, sb, tid, acc);

    const int base64 = n0 + wn;
    if ((base64 / 64) % 3 != 2) {
        // nope columns
#pragma unroll
        for (int mt = 0; mt < 2; mt++)
#pragma unroll
            for (int half_i = 0; half_i < 2; half_i++) {
                const int row = m0 + wm + mt * 16 + (lane >> 2) + half_i * 8;
#pragma unroll
                for (int nt = 0; nt < 8; nt++) {
                    const int c = base64 + nt * 8 + (lane & 3) * 2;
                    const int h = c / 192;
                    const int cr = c - h * 192;
                    const size_t o = ((size_t)h * S_LEN + row) * DQK + cr;
                    __half h0, l0, h1, l1;
                    split_h(acc[mt][nt][half_i * 2], h0, l0);
                    split_h(acc[mt][nt][half_i * 2 + 1], h1, l1);
                    *reinterpret_cast<__half2*>(Qh + o) = __half2(h0, h1);
                    *reinterpret_cast<__half2*>(Ql + o) = __half2(l0, l1);
                }
            }
    } else {
        // pe columns: d in [0,64), rotate with partner at nt^4
        const int h = base64 / 192;
#pragma unroll
        for (int mt = 0; mt < 2; mt++)
#pragma unroll
            for (int half_i = 0; half_i < 2; half_i++) {
                const int row = m0 + wm + mt * 16 + (lane >> 2) + half_i * 8;
                const size_t rb = ((size_t)h * S_LEN + row) * DQK + 128;
#pragma unroll
                for (int ntL = 0; ntL < 4; ntL++) {
                    const int d0 = ntL * 8 + (lane & 3) * 2;
                    float o0[2], o1[2];
#pragma unroll
                    for (int e = 0; e < 2; e++) {
                        float cc, ss;
                        rope_cs(row, d0 + e, cc, ss);
                        const float v1 = acc[mt][ntL][half_i * 2 + e];
                        const float v2 = acc[mt][ntL + 4][half_i * 2 + e];
                        o0[e] = v1 * cc - v2 * ss;
                        o1[e] = v2 * cc + v1 * ss;
                    }
                    __half h0, l0, h1, l1;
                    split_h(o0[0], h0, l0); split_h(o0[1], h1, l1);
                    *reinterpret_cast<__half2*>(Qh + rb + d0) = __half2(h0, h1);
                    *reinterpret_cast<__half2*>(Ql + rb + d0) = __half2(l0, l1);
                    split_h(o1[0], h0, l0); split_h(o1[1], h1, l1);
                    *reinterpret_cast<__half2*>(Qh + rb + d0 + 32) = __half2(h0, h1);
                    *reinterpret_cast<__half2*>(Ql + rb + d0 + 32) = __half2(l0, l1);
                }
            }
    }
}

// ---------------- kv GEMM: 2-pass, k_nope -> split per-head; v -> fp32 ----------
__global__ __launch_bounds__(256, 1) void mma_gemm_kv(
    const __half* __restrict__ Ah, const __half* __restrict__ Al,
    const __half* __restrict__ Bh,
    __half* __restrict__ Kh, __half* __restrict__ Kl, float* __restrict__ kv)
{
    GEMM_PROLOGUE();
    gemm_body<2>(Ah, Al, Bh, nullptr, KVLORA, KVLORA >> 6, m0, n0, sb, tid, acc);

    const int base64 = n0 + wn;
    const int blk4 = (base64 / 64) & 3;
    if (blk4 < 2) {
        const int h = base64 / 256;
#pragma unroll
        for (int mt = 0; mt < 2; mt++)
#pragma unroll
            for (int half_i = 0; half_i < 2; half_i++) {
                const int row = m0 + wm + mt * 16 + (lane >> 2) + half_i * 8;
#pragma unroll
                for (int nt = 0; nt < 8; nt++) {
                    const int c = base64 + nt * 8 + (lane & 3) * 2;
                    const int cr = c - h * 256;           // < 128
                    const size_t o = ((size_t)h * S_LEN + row) * DQK + cr;
                    __half h0, l0, h1, l1;
                    split_h(acc[mt][nt][half_i * 2], h0, l0);
                    split_h(acc[mt][nt][half_i * 2 + 1], h1, l1);
                    *reinterpret_cast<__half2*>(Kh + o) = __half2(h0, h1);
                    *reinterpret_cast<__half2*>(Kl + o) = __half2(l0, l1);
                }
            }
    } else {
#pragma unroll
        for (int mt = 0; mt < 2; mt++) {
            const int row = m0 + wm + mt * 16 + (lane >> 2);
#pragma unroll
            for (int nt = 0; nt < 8; nt++) {
                const int c = base64 + nt * 8 + (lane & 3) * 2;
                *reinterpret_cast<float2*>(kv + (size_t)row * KVD + c) =
                    make_float2(acc[mt][nt][0], acc[mt][nt][1]);
                *reinterpret_cast<float2*>(kv + (size_t)(row + 8) * KVD + c) =
                    make_float2(acc[mt][nt][2], acc[mt][nt][3]);
            }
        }
    }
}

// ---------------- score GEMM (3-pass) ----------------
__global__ __launch_bounds__(256, 1) void score_mma(
    const __half* __restrict__ Qh, const __half* __restrict__ Ql,
    const __half* __restrict__ Kh, const __half* __restrict__ Kl,
    float* __restrict__ attn)
{
    const int jt = blockIdx.x, it = blockIdx.y, h = blockIdx.z;
    if (jt > it) return;
    extern __shared__ __align__(128) char smem[];
    const uint32_t sb = smem_u32(smem);
    const int tid = threadIdx.x;
    const int lane = tid & 31;
    const int wid = tid >> 5;
    const int m0 = it * 128, n0 = jt * 128;
    const int wm = (wid & 3) * 32, wn = (wid >> 2) * 64;
    const size_t hoff = (size_t)h * S_LEN * DQK;

    float acc[2][8][4];
#pragma unroll
    for (int mt = 0; mt < 2; mt++)
#pragma unroll
        for (int nt = 0; nt < 8; nt++)
#pragma unroll
            for (int e = 0; e < 4; e++) acc[mt][nt][e] = 0.0f;

    gemm_body<3>(Qh + hoff, Ql + hoff, Kh + hoff, Kl + hoff, DQK, 3, m0, n0, sb, tid, acc);

    const float scale = 0.07216878364870323f;
    float* C = attn + (((size_t)h) << 20);
#pragma unroll
    for (int mt = 0; mt < 2; mt++) {
        const int row = m0 + wm + mt * 16 + (lane >> 2);
#pragma unroll
        for (int nt = 0; nt < 8; nt++) {
            const int col = n0 + wn + nt * 8 + (lane & 3) * 2;
            *reinterpret_cast<float2*>(C + (size_t)row * S_LEN + col) =
                make_float2(acc[mt][nt][0] * scale, acc[mt][nt][1] * scale);
            *reinterpret_cast<float2*>(C + (size_t)(row + 8) * S_LEN + col) =
                make_float2(acc[mt][nt][2] * scale, acc[mt][nt][3] * scale);
        }
    }
}

// ---------------- AV GEMM (3-pass), ctx -> single fp16 ----------------
__global__ __launch_bounds__(256, 1) void av_mma(
    const __half* __restrict__ Ph, const __half* __restrict__ Pl,
    const __half* __restrict__ Vth, const __half* __restrict__ Vtl,
    const float* __restrict__ inv_sum, __half* __restrict__ ch)
{
    const int it = blockIdx.y, h = blockIdx.z;
    extern __shared__ __align__(128) char smem[];
    const uint32_t sb = smem_u32(smem);
    const int tid = threadIdx.x;
    const int lane = tid & 31;
    const int wid = tid >> 5;
    const int m0 = it * 128;
    const int wm = (wid & 3) * 32, wn = (wid >> 2) * 64;

    float acc[2][8][4];
#pragma unroll
    for (int mt = 0; mt < 2; mt++)
#pragma unroll
        for (int nt = 0; nt < 8; nt++)
#pragma unroll
            for (int e = 0; e < 4; e++) acc[mt][nt][e] = 0.0f;

    const size_t poff = ((size_t)h) << 20;
    const size_t voff = (size_t)h * DV * S_LEN;
    gemm_body<3>(Ph + poff, Pl + poff, Vth + voff, Vtl + voff,
                 S_LEN, (it + 1) * 2, m0, 0, sb, tid, acc);

#pragma unroll
    for (int mt = 0; mt < 2; mt++)
#pragma unroll
        for (int half_i = 0; half_i < 2; half_i++) {
            const int row = m0 + wm + mt * 16 + (lane >> 2) + half_i * 8;
            const float inv = inv_sum[h * S_LEN + row];
#pragma unroll
            for (int nt = 0; nt < 8; nt++) {
                const int col = wn + nt * 8 + (lane & 3) * 2;
                const size_t o = (size_t)row * CTX_D + (size_t)h * DV + col;
                *reinterpret_cast<__half2*>(ch + o) =
                    __half2(__float2half_rn(acc[mt][nt][half_i * 2] * inv),
                            __float2half_rn(acc[mt][nt][half_i * 2 + 1] * inv));
            }
        }
}

// ---------------- weight converts ----------------
__global__ void conv_w(const float* __restrict__ W, __half* __restrict__ Th, int K, int N)
{
    __shared__ float t[32][33];
    const int k0 = blockIdx.x * 32, n0 = blockIdx.y * 32;
    const int tx = threadIdx.x, ty = threadIdx.y;
#pragma unroll
    for (int i = 0; i < 4; i++) {
        const int k = k0 + ty + i * 8;
        const int n = n0 + tx;
        t[ty + i * 8][tx] = (n < N) ? W[(size_t)k * N + n] : 0.0f;
    }
    __syncthreads();
#pragma unroll
    for (int i = 0; i < 4; i++)
        Th[(size_t)(n0 + ty + i * 8) * K + k0 + tx] = __float2half_rn(t[tx][ty + i * 8]);
}

__global__ void conv_w_split(const float* __restrict__ W, __half* __restrict__ Th,
                             __half* __restrict__ Tl, int K, int N)
{
    __shared__ float t[32][33];
    const int k0 = blockIdx.x * 32, n0 = blockIdx.y * 32;
    const int tx = threadIdx.x, ty = threadIdx.y;
#pragma unroll
    for (int i = 0; i < 4; i++) {
        const int k = k0 + ty + i * 8;
        const int n = n0 + tx;
        t[ty + i * 8][tx] = (n < N) ? W[(size_t)k * N + n] : 0.0f;
    }
    __syncthreads();
#pragma unroll
    for (int i = 0; i < 4; i++) {
        __half h, l;
        split_h(t[tx][ty + i * 8], h, l);
        Th[(size_t)(n0 + ty + i * 8) * K + k0 + tx] = h;
        Tl[(size_t)(n0 + ty + i * 8) * K + k0 + tx] = l;
    }
}

// ---------------- activation convert ----------------
__global__ void conv_a(const float* __restrict__ A, __half* __restrict__ H,
                       __half* __restrict__ L, int n4)
{
    const int i = blockIdx.x * blockDim.x + threadIdx.x;
    if (i >= n4) return;
    const float4 v = reinterpret_cast<const float4*>(A)[i];
    __half h0, l0, h1, l1, h2, l2, h3, l3;
    split_h(v.x, h0, l0); split_h(v.y, h1, l1);
    split_h(v.z, h2, l2); split_h(v.w, h3, l3);
    __half2* Hp = reinterpret_cast<__half2*>(H) + i * 2;
    __half2* Lp = reinterpret_cast<__half2*>(L) + i * 2;
    Hp[0] = __half2(h0, h1); Hp[1] = __half2(h2, h3);
    Lp[0] = __half2(l0, l1); Lp[1] = __half2(l2, l3);
}

// ---------------- rmsnorm fused to fp16 hi/lo ----------------
__global__ void rmsnorm_h(const float* __restrict__ x, const float* __restrict__ gamma,
                          __half* __restrict__ yh, __half* __restrict__ yl,
                          int D, int xstride)
{
    const int row = blockIdx.x;
    const float* xr = x + (size_t)row * xstride;
    float s = 0.0f;
    for (int i = threadIdx.x; i < D; i += 256) { const float v = xr[i]; s += v * v; }
    __shared__ float red[256];
    red[threadIdx.x] = s;
    __syncthreads();
    for (int o = 128; o > 0; o >>= 1) {
        if (threadIdx.x < o) red[threadIdx.x] += red[threadIdx.x + o];
        __syncthreads();
    }
    const float inv = rsqrtf(red[0] / (float)D + 1e-6f);
    for (int i = threadIdx.x; i < D; i += 256) {
        __half h, l;
        split_h(xr[i] * inv * gamma[i], h, l);
        yh[(size_t)row * D + i] = h;
        yl[(size_t)row * D + i] = l;
    }
}

// ---------------- k_pe RoPE ----------------
__global__ void rope_k_kernel(const float* __restrict__ comp, float* __restrict__ kpe)
{
    const int t = blockIdx.x * blockDim.x + threadIdx.x;
    if (t >= S_LEN * 32) return;
    const int d = t & 31;
    const int s = t >> 5;
    float c, sn;
    rope_cs(s, d, c, sn);
    const float* src = comp + (size_t)s * COMP_D + QLORA + KVLORA;
    const float x1 = src[d], x2 = src[d + 32];
    kpe[s * DR + d]      = x1 * c - x2 * sn;
    kpe[s * DR + d + 32] = x2 * c + x1 * sn;
}

// ---------------- broadcast roped k_pe into per-head K cols 128..191 -----------
__global__ void fill_kpe(const float* __restrict__ kpe,
                         __half* __restrict__ Kh, __half* __restrict__ Kl)
{
    const int t = blockIdx.x * blockDim.x + threadIdx.x;
    if (t >= NH * S_LEN * 32) return;
    const int d2 = t & 31;
    const int j  = (t >> 5) & (S_LEN - 1);
    const int h  = t >> 15;
    const int d = d2 * 2;
    __half h0, l0, h1, l1;
    split_h(kpe[j * DR + d], h0, l0);
    split_h(kpe[j * DR + d + 1], h1, l1);
    const size_t o = ((size_t)h * S_LEN + j) * DQK + 128 + d;
    *reinterpret_cast<__half2*>(Kh + o) = __half2(h0, h1);
    *reinterpret_cast<__half2*>(Kl + o) = __half2(l0, l1);
}

// ---------------- build V^T per head (transpose + split) ----------------
__global__ void build_vt(const float* __restrict__ kv,
                         __half* __restrict__ Vth, __half* __restrict__ Vtl)
{
    __shared__ float t[32][33];
    const int j0 = blockIdx.x * 32, d0 = blockIdx.y * 32, h = blockIdx.z;
    const int tx = threadIdx.x, ty = threadIdx.y;
#pragma unroll
    for (int i = 0; i < 4; i++)
        t[ty + i * 8][tx] = kv[(size_t)(j0 + ty + i * 8) * KVD + h * 256 + 128 + d0 + tx];
    __syncthreads();
    const size_t base = (size_t)h * DV * S_LEN;
#pragma unroll
    for (int i = 0; i < 4; i++) {
        const int d = d0 + ty + i * 8;
        const int j = j0 + tx;
        __half hh, ll;
        split_h(t[tx][ty + i * 8], hh, ll);
        Vth[base + (size_t)d * S_LEN + j] = hh;
        Vtl[base + (size_t)d * S_LEN + j] = ll;
    }
}

// ---------------- softmax: unnormalized exp -> ph/pl fp16, inv_sum ----------------
__global__ void softmax_split(const float* __restrict__ attn,
                              __half* __restrict__ Ph, __half* __restrict__ Pl,
                              float* __restrict__ inv_sum)
{
    const int i = blockIdx.x, h = blockIdx.y;
    const size_t base = (((size_t)h) << 20) + (size_t)i * S_LEN;
    const int len = i + 1;
    const int kend = ((i >> 7) + 1) * 128;
    __shared__ float red[256];

    float m = -3.4e38f;
    for (int j = threadIdx.x; j < len; j += 256) m = fmaxf(m, attn[base + j]);
    red[threadIdx.x] = m;
    __syncthreads();
    for (int o = 128; o > 0; o >>= 1) {
        if (threadIdx.x < o) red[threadIdx.x] = fmaxf(red[threadIdx.x], red[threadIdx.x + o]);
        __syncthreads();
    }
    m = red[0];
    __syncthreads();

    float s = 0.0f;
    for (int j = threadIdx.x; j < len; j += 256) {
        const float p = __expf(attn[base + j] - m);
        s += p;
        __half hh, ll;
        split_h(p, hh, ll);
        Ph[base + j] = hh;
        Pl[base + j] = ll;
    }
    for (int j = len + threadIdx.x; j < kend; j += 256) {
        Ph[base + j] = __float2half_rn(0.0f);
        Pl[base + j] = __float2half_rn(0.0f);
    }
    red[threadIdx.x] = s;
    __syncthreads();
    for (int o = 128; o > 0; o >>= 1) {
        if (threadIdx.x < o) red[threadIdx.x] += red[threadIdx.x + o];
        __syncthreads();
    }
    if (threadIdx.x == 0) inv_sum[h * S_LEN + i] = 1.0f / red[0];
}

// ---------------- launch ----------------
extern "C" void kernel_launch(void* const* d_in, const int* in_sizes, int n_in,
                              void* d_out, int out_size)
{
    const float* hs       = (const float*)d_in[0];
    const float* w_kv_a   = (const float*)d_in[1];
    const float* q_gamma  = (const float*)d_in[2];
    const float* kv_gamma = (const float*)d_in[3];
    const float* w_q_b    = (const float*)d_in[4];
    const float* w_kv_b   = (const float*)d_in[5];
    const float* w_o      = (const float*)d_in[6];
    float* out = (float*)d_out;

    float *comp, *kv, *kpe, *attn, *inv;
    __half *ah, *al, *wh, *wla, *qh, *ql, *kh, *kl, *vth, *vtl, *ph, *pl;
    cudaGetSymbolAddress((void**)&comp, g_comp);
    cudaGetSymbolAddress((void**)&ah,   g_ah);
    cudaGetSymbolAddress((void**)&al,   g_al);
    cudaGetSymbolAddress((void**)&wh,   g_wh);
    cudaGetSymbolAddress((void**)&wla,  g_wla);
    cudaGetSymbolAddress((void**)&kv,   g_kv);
    cudaGetSymbolAddress((void**)&kpe,  g_kpe);
    cudaGetSymbolAddress((void**)&attn, g_attn);
    cudaGetSymbolAddress((void**)&qh,   g_qh);
    cudaGetSymbolAddress((void**)&ql,   g_ql);
    cudaGetSymbolAddress((void**)&kh,   g_kh);
    cudaGetSymbolAddress((void**)&kl,   g_kl);
    cudaGetSymbolAddress((void**)&vth,  g_vth);
    cudaGetSymbolAddress((void**)&vtl,  g_vtl);
    cudaGetSymbolAddress((void**)&ph,   g_ph);
    cudaGetSymbolAddress((void**)&pl,   g_pl);
    cudaGetSymbolAddress((void**)&inv,  g_inv);

    cudaFuncSetAttribute(mma_gemm3, cudaFuncAttributeMaxDynamicSharedMemorySize, 131072);
    cudaFuncSetAttribute(mma_gemm_q, cudaFuncAttributeMaxDynamicSharedMemorySize, 98304);
    cudaFuncSetAttribute(mma_gemm_kv, cudaFuncAttributeMaxDynamicSharedMemorySize, 98304);
    cudaFuncSetAttribute(mma_gemm1, cudaFuncAttributeMaxDynamicSharedMemorySize, 65536);
    cudaFuncSetAttribute(score_mma, cudaFuncAttributeMaxDynamicSharedMemorySize, 131072);
    cudaFuncSetAttribute(av_mma, cudaFuncAttributeMaxDynamicSharedMemorySize, 131072);
    const dim3 T256(256);
    const dim3 TW(32, 8);

    // 1) comp = hs @ w_kv_a  (3-pass; N pad 2176)
    conv_a<<<(S_LEN * HID_D / 4 + 255) / 256, 256>>>(hs, ah, al, S_LEN * HID_D / 4);
    conv_w_split<<<dim3(HID_D / 32, 2176 / 32), TW>>>(w_kv_a, wh, wla, HID_D, COMP_D);
    mma_gemm3<<<dim3(17, 8), T256, 131072>>>(ah, al, wh, wla, comp, COMP_D, HID_D);

    // 2) k_pe RoPE
    rope_k_kernel<<<(S_LEN * 32) / 256, 256>>>(comp, kpe);

    // 3) q = rmsnorm(q_c) @ w_q_b, fused RoPE+split -> per-head Qh/Ql
    rmsnorm_h<<<S_LEN, 256>>>(comp, q_gamma, ah, al, QLORA, COMP_D);
    conv_w<<<dim3(QLORA / 32, QD / 32), TW>>>(w_q_b, wh, QLORA, QD);
    mma_gemm_q<<<dim3(QD / 128, 8), T256, 98304>>>(ah, al, wh, qh, ql);

    // 4) kv = rmsnorm(kv_c) @ w_kv_b, fused split -> Kh/Kl (nope) + kv fp32 (v)
    rmsnorm_h<<<S_LEN, 256>>>(comp + QLORA, kv_gamma, ah, al, KVLORA, COMP_D);
    conv_w<<<dim3(KVLORA / 32, KVD / 32), TW>>>(w_kv_b, wh, KVLORA, KVD);
    mma_gemm_kv<<<dim3(KVD / 128, 8), T256, 98304>>>(ah, al, wh, kh, kl, kv);
    fill_kpe<<<(NH * S_LEN * 32) / 256, 256>>>(kpe, kh, kl);
    build_vt<<<dim3(32, 4, NH), TW>>>(kv, vth, vtl);

    // 5) attention
    score_mma<<<dim3(8, 8, NH), T256, 131072>>>(qh, ql, kh, kl, attn);
    softmax_split<<<dim3(S_LEN, NH), 256>>>(attn, ph, pl, inv);
    av_mma<<<dim3(1, 8, NH), T256, 131072>>>(ph, pl, vth, vtl, inv, ah);   // ctx fp16

    // 6) out = ctx @ w_o  (1-pass)
    conv_w<<<dim3(CTX_D / 32, HID_D / 32), TW>>>(w_o, wh, CTX_D, HID_D);
    mma_gemm1<<<dim3(HID_D / 128, 8), T256, 65536>>>(ah, wh, out, HID_D, CTX_D);
}

// round 7
// speedup vs baseline: 5.6863x; 1.0282x over previous
#include <cuda_runtime.h>
#include <cuda_fp16.h>
#include <math.h>
#include <stdint.h>

// ---------------- problem constants ----------------
#define S_LEN 1024
#define HID_D 7168
#define NH 128
#define DN 128
#define DR 64
#define DV 128
#define QLORA 1536
#define KVLORA 512
#define COMP_D (QLORA + KVLORA + DR)      // 2112
#define QD (NH * (DN + DR))               // 24576
#define KVD (NH * (DN + DV))              // 32768
#define CTX_D (NH * DV)                   // 16384
#define DQK 192

// ---------------- scratch (device globals) ----------------
__device__ float g_comp[S_LEN * COMP_D];
__device__ __half g_ah[(size_t)S_LEN * 16384];                   // activations hi (also ctx)
__device__ __half g_al[(size_t)S_LEN * 16384];                   // activations lo
__device__ __half g_wa_h[15597568];                              // w_kv_a hi (2176*7168)
__device__ __half g_wa_l[15597568];                              // w_kv_a lo
__device__ __half g_wq[(size_t)QD * QLORA];                      // w_q_b^T
__device__ __half g_wkv[(size_t)KVD * KVLORA];                   // w_kv_b^T
__device__ __half g_wo[(size_t)HID_D * CTX_D];                   // w_o^T
__device__ float g_kv[(size_t)S_LEN * KVD];                      // v half only used
__device__ float g_kpe[S_LEN * DR];
__device__ float g_attn[(size_t)NH * S_LEN * S_LEN];
__device__ __half g_qh[(size_t)NH * S_LEN * DQK];
__device__ __half g_ql[(size_t)NH * S_LEN * DQK];
__device__ __half g_kh[(size_t)NH * S_LEN * DQK];
__device__ __half g_kl[(size_t)NH * S_LEN * DQK];
__device__ __half g_vth[(size_t)NH * DV * S_LEN];
__device__ __half g_ph[(size_t)NH * S_LEN * S_LEN];
__device__ __half g_pl[(size_t)NH * S_LEN * S_LEN];
__device__ float g_inv[NH * S_LEN];

// ---------------- PTX helpers ----------------
__device__ __forceinline__ uint32_t smem_u32(const void* p) {
    uint32_t a;
    asm("{ .reg .u64 t; cvta.to.shared.u64 t, %1; cvt.u32.u64 %0, t; }" : "=r"(a) : "l"(p));
    return a;
}
#define CP16(dst, src) \
    asm volatile("cp.async.cg.shared.global [%0], [%1], 16;" :: "r"(dst), "l"(src) : "memory")
#define CP_COMMIT() asm volatile("cp.async.commit_group;" ::: "memory")
#define CP_WAIT1() asm volatile("cp.async.wait_group 1;" ::: "memory")
#define CP_WAIT0() asm volatile("cp.async.wait_group 0;" ::: "memory")

#define LDSM4(r, a) \
    asm volatile("ldmatrix.sync.aligned.m8n8.x4.shared.b16 {%0,%1,%2,%3}, [%4];" \
        : "=r"((r)[0]), "=r"((r)[1]), "=r"((r)[2]), "=r"((r)[3]) : "r"(a))

#define MMA_F16(d, a, b0, b1) \
    asm volatile("mma.sync.aligned.m16n8k16.row.col.f32.f16.f16.f32 " \
        "{%0,%1,%2,%3}, {%4,%5,%6,%7}, {%8,%9}, {%0,%1,%2,%3};" \
        : "+f"((d)[0]), "+f"((d)[1]), "+f"((d)[2]), "+f"((d)[3]) \
        : "r"((a)[0]), "r"((a)[1]), "r"((a)[2]), "r"((a)[3]), "r"(b0), "r"(b1))

#define SWZ(o) ((o) ^ (((o) >> 3) & 0x70))

__device__ __forceinline__ void split_h(float v, __half& h, __half& l) {
    h = __float2half_rn(v);
    l = __float2half_rn(v - __half2float(h));
}

// ---------------- shared GEMM body ----------------
// NPASS=1: ah*bh        NPASS=2: ah*bh + al*bh        NPASS=3: + ah*bl
template <int NPASS>
__device__ __forceinline__ void gemm_body(
    const __half* __restrict__ Ah, const __half* __restrict__ Al,
    const __half* __restrict__ Bh, const __half* __restrict__ Bl,
    int K, int nch, int m0, int n0, uint32_t sb, int tid, float acc[2][8][4])
{
    constexpr int CA = (NPASS >= 2) ? 2 : 1;
    constexpr int CB = (NPASS == 3) ? 2 : 1;
    constexpr int NT = CA + CB;
    constexpr int STAGE = NT * 16384;
    const int lane = tid & 31;
    const int wid = tid >> 5;
    const int wm = (wid & 3) * 32;
    const int wn = (wid >> 2) * 64;

    auto load_stage = [&](int c, int s) {
        const int kc = c << 6;
#pragma unroll
        for (int it = 0; it < NT * 4; it++) {
            const int t = tid + it * 256;
            const int tensor = t >> 10;
            const int rem = t & 1023;
            const int row = rem >> 3;
            const int ch = rem & 7;
            const __half* src;
            int grow;
            if (tensor < CA) {
                src = (CA == 2 && tensor == 1) ? Al : Ah;
                grow = m0 + row;
            } else {
                src = (CB == 2 && tensor == CA + 1) ? Bl : Bh;
                grow = n0 + row;
            }
            const __half* sp = src + (size_t)grow * K + kc + ch * 8;
            const uint32_t dst = sb + s * STAGE + tensor * 16384 + SWZ(row * 128 + ch * 16);
            CP16(dst, sp);
        }
        CP_COMMIT();
    };

    load_stage(0, 0);

    for (int c = 0; c < nch; c++) {
        const int buf = c & 1;
        if (c + 1 < nch) { load_stage(c + 1, buf ^ 1); CP_WAIT1(); }
        else             { CP_WAIT0(); }
        __syncthreads();

        const uint32_t st = sb + buf * STAGE;
        const uint32_t sA_h = st;
        const uint32_t sA_l = st + 16384;
        const uint32_t sB_h = st + CA * 16384;
        const uint32_t sB_l = sB_h + 16384;
        const int rl = lane & 15;
        const int kb = lane >> 4;

#pragma unroll
        for (int k16 = 0; k16 < 4; k16++) {
            const int kbyte = k16 * 32 + kb * 16;
            uint32_t afh[2][4], afl[2][4], bfh[4][4], bfl[4][4];
#pragma unroll
            for (int mt = 0; mt < 2; mt++) {
                const uint32_t off = SWZ((wm + mt * 16 + rl) * 128 + kbyte);
                LDSM4(afh[mt], sA_h + off);
                if (CA == 2) LDSM4(afl[mt], sA_l + off);
            }
#pragma unroll
            for (int q = 0; q < 4; q++) {
                const uint32_t off = SWZ((wn + q * 16 + rl) * 128 + kbyte);
                LDSM4(bfh[q], sB_h + off);
                if (CB == 2) LDSM4(bfl[q], sB_l + off);
            }
#pragma unroll
            for (int mt = 0; mt < 2; mt++)
#pragma unroll
                for (int nt = 0; nt < 8; nt++) {
                    const int q = nt >> 1, s = nt & 1;
                    MMA_F16(acc[mt][nt], afh[mt], bfh[q][s], bfh[q][s + 2]);
                    if (CA == 2) MMA_F16(acc[mt][nt], afl[mt], bfh[q][s], bfh[q][s + 2]);
                    if (CB == 2) MMA_F16(acc[mt][nt], afh[mt], bfl[q][s], bfl[q][s + 2]);
                }
        }
        __syncthreads();
    }
}

#define GEMM_PROLOGUE() \
    extern __shared__ __align__(128) char smem[]; \
    const uint32_t sb = smem_u32(smem); \
    const int tid = threadIdx.x; \
    const int lane = tid & 31; \
    const int wid = tid >> 5; \
    const int m0 = blockIdx.y * 128, n0 = blockIdx.x * 128; \
    const int wm = (wid & 3) * 32, wn = (wid >> 2) * 64; \
    float acc[2][8][4]; \
    _Pragma("unroll") for (int mt = 0; mt < 2; mt++) \
    _Pragma("unroll") for (int nt = 0; nt < 8; nt++) \
    _Pragma("unroll") for (int e = 0; e < 4; e++) acc[mt][nt][e] = 0.0f;

// ---------------- comp GEMM: 3-pass, fp32 out ----------------
__global__ __launch_bounds__(256, 1) void mma_gemm3(
    const __half* __restrict__ Ah, const __half* __restrict__ Al,
    const __half* __restrict__ Bh, const __half* __restrict__ Bl,
    float* __restrict__ C, int N, int K)
{
    GEMM_PROLOGUE();
    gemm_body<3>(Ah, Al, Bh, Bl, K, K >> 6, m0, n0, sb, tid, acc);
#pragma unroll
    for (int mt = 0; mt < 2; mt++) {
        const int row = m0 + wm + mt * 16 + (lane >> 2);
#pragma unroll
        for (int nt = 0; nt < 8; nt++) {
            const int col = n0 + wn + nt * 8 + (lane & 3) * 2;
            if (col < N) {
                *reinterpret_cast<float2*>(C + (size_t)row * N + col) =
                    make_float2(acc[mt][nt][0], acc[mt][nt][1]);
                *reinterpret_cast<float2*>(C + (size_t)(row + 8) * N + col) =
                    make_float2(acc[mt][nt][2], acc[mt][nt][3]);
            }
        }
    }
}

// ---------------- w_o GEMM: 1-pass, fp32 out ----------------
__global__ __launch_bounds__(256, 1) void mma_gemm1(
    const __half* __restrict__ Ah, const __half* __restrict__ Bh,
    float* __restrict__ C, int N, int K)
{
    GEMM_PROLOGUE();
    gemm_body<1>(Ah, nullptr, Bh, nullptr, K, K >> 6, m0, n0, sb, tid, acc);
#pragma unroll
    for (int mt = 0; mt < 2; mt++) {
        const int row = m0 + wm + mt * 16 + (lane >> 2);
#pragma unroll
        for (int nt = 0; nt < 8; nt++) {
            const int col = n0 + wn + nt * 8 + (lane & 3) * 2;
            *reinterpret_cast<float2*>(C + (size_t)row * N + col) =
                make_float2(acc[mt][nt][0], acc[mt][nt][1]);
            *reinterpret_cast<float2*>(C + (size_t)(row + 8) * N + col) =
                make_float2(acc[mt][nt][2], acc[mt][nt][3]);
        }
    }
}

// ---------------- RoPE angle ----------------
__device__ __forceinline__ void rope_cs(int s, int d, float& c, float& sn)
{
    const float inv = exp2f(-(float)d * (13.287712379549449f / 32.0f));
    sincosf((float)s * inv, &sn, &c);
}

// ---------------- q GEMM: 2-pass, fused RoPE + split, per-head layout -----------
__global__ __launch_bounds__(256, 1) void mma_gemm_q(
    const __half* __restrict__ Ah, const __half* __restrict__ Al,
    const __half* __restrict__ Bh,
    __half* __restrict__ Qh, __half* __restrict__ Ql)
{
    GEMM_PROLOGUE();
    gemm_body<2>(Ah, Al, Bh, nullptr, QLORA, QLORA >> 6, m0, n0, sb, tid, acc);

    const int base64 = n0 + wn;
    if ((base64 / 64) % 3 != 2) {
#pragma unroll
        for (int mt = 0; mt < 2; mt++)
#pragma unroll
            for (int half_i = 0; half_i < 2; half_i++) {
                const int row = m0 + wm + mt * 16 + (lane >> 2) + half_i * 8;
#pragma unroll
                for (int nt = 0; nt < 8; nt++) {
                    const int c = base64 + nt * 8 + (lane & 3) * 2;
                    const int h = c / 192;
                    const int cr = c - h * 192;
                    const size_t o = ((size_t)h * S_LEN + row) * DQK + cr;
                    __half h0, l0, h1, l1;
                    split_h(acc[mt][nt][half_i * 2], h0, l0);
                    split_h(acc[mt][nt][half_i * 2 + 1], h1, l1);
                    *reinterpret_cast<__half2*>(Qh + o) = __half2(h0, h1);
                    *reinterpret_cast<__half2*>(Ql + o) = __half2(l0, l1);
                }
            }
    } else {
        const int h = base64 / 192;
#pragma unroll
        for (int mt = 0; mt < 2; mt++)
#pragma unroll
            for (int half_i = 0; half_i < 2; half_i++) {
                const int row = m0 + wm + mt * 16 + (lane >> 2) + half_i * 8;
                const size_t rb = ((size_t)h * S_LEN + row) * DQK + 128;
#pragma unroll
                for (int ntL = 0; ntL < 4; ntL++) {
                    const int d0 = ntL * 8 + (lane & 3) * 2;
                    float o0[2], o1[2];
#pragma unroll
                    for (int e = 0; e < 2; e++) {
                        float cc, ss;
                        rope_cs(row, d0 + e, cc, ss);
                        const float v1 = acc[mt][ntL][half_i * 2 + e];
                        const float v2 = acc[mt][ntL + 4][half_i * 2 + e];
                        o0[e] = v1 * cc - v2 * ss;
                        o1[e] = v2 * cc + v1 * ss;
                    }
                    __half h0, l0, h1, l1;
                    split_h(o0[0], h0, l0); split_h(o0[1], h1, l1);
                    *reinterpret_cast<__half2*>(Qh + rb + d0) = __half2(h0, h1);
                    *reinterpret_cast<__half2*>(Ql + rb + d0) = __half2(l0, l1);
                    split_h(o1[0], h0, l0); split_h(o1[1], h1, l1);
                    *reinterpret_cast<__half2*>(Qh + rb + d0 + 32) = __half2(h0, h1);
                    *reinterpret_cast<__half2*>(Ql + rb + d0 + 32) = __half2(l0, l1);
                }
            }
    }
}

// ---------------- kv GEMM: 2-pass, k_nope -> split per-head; v -> fp32 ----------
__global__ __launch_bounds__(256, 1) void mma_gemm_kv(
    const __half* __restrict__ Ah, const __half* __restrict__ Al,
    const __half* __restrict__ Bh,
    __half* __restrict__ Kh, __half* __restrict__ Kl, float* __restrict__ kv)
{
    GEMM_PROLOGUE();
    gemm_body<2>(Ah, Al, Bh, nullptr, KVLORA, KVLORA >> 6, m0, n0, sb, tid, acc);

    const int base64 = n0 + wn;
    const int blk4 = (base64 / 64) & 3;
    if (blk4 < 2) {
        const int h = base64 / 256;
#pragma unroll
        for (int mt = 0; mt < 2; mt++)
#pragma unroll
            for (int half_i = 0; half_i < 2; half_i++) {
                const int row = m0 + wm + mt * 16 + (lane >> 2) + half_i * 8;
#pragma unroll
                for (int nt = 0; nt < 8; nt++) {
                    const int c = base64 + nt * 8 + (lane & 3) * 2;
                    const int cr = c - h * 256;
                    const size_t o = ((size_t)h * S_LEN + row) * DQK + cr;
                    __half h0, l0, h1, l1;
                    split_h(acc[mt][nt][half_i * 2], h0, l0);
                    split_h(acc[mt][nt][half_i * 2 + 1], h1, l1);
                    *reinterpret_cast<__half2*>(Kh + o) = __half2(h0, h1);
                    *reinterpret_cast<__half2*>(Kl + o) = __half2(l0, l1);
                }
            }
    } else {
#pragma unroll
        for (int mt = 0; mt < 2; mt++) {
            const int row = m0 + wm + mt * 16 + (lane >> 2);
#pragma unroll
            for (int nt = 0; nt < 8; nt++) {
                const int c = base64 + nt * 8 + (lane & 3) * 2;
                *reinterpret_cast<float2*>(kv + (size_t)row * KVD + c) =
                    make_float2(acc[mt][nt][0], acc[mt][nt][1]);
                *reinterpret_cast<float2*>(kv + (size_t)(row + 8) * KVD + c) =
                    make_float2(acc[mt][nt][2], acc[mt][nt][3]);
            }
        }
    }
}

// ---------------- score GEMM (3-pass) ----------------
__global__ __launch_bounds__(256, 1) void score_mma(
    const __half* __restrict__ Qh, const __half* __restrict__ Ql,
    const __half* __restrict__ Kh, const __half* __restrict__ Kl,
    float* __restrict__ attn)
{
    const int jt = blockIdx.x, it = blockIdx.y, h = blockIdx.z;
    if (jt > it) return;
    extern __shared__ __align__(128) char smem[];
    const uint32_t sb = smem_u32(smem);
    const int tid = threadIdx.x;
    const int lane = tid & 31;
    const int wid = tid >> 5;
    const int m0 = it * 128, n0 = jt * 128;
    const int wm = (wid & 3) * 32, wn = (wid >> 2) * 64;
    const size_t hoff = (size_t)h * S_LEN * DQK;

    float acc[2][8][4];
#pragma unroll
    for (int mt = 0; mt < 2; mt++)
#pragma unroll
        for (int nt = 0; nt < 8; nt++)
#pragma unroll
            for (int e = 0; e < 4; e++) acc[mt][nt][e] = 0.0f;

    gemm_body<3>(Qh + hoff, Ql + hoff, Kh + hoff, Kl + hoff, DQK, 3, m0, n0, sb, tid, acc);

    const float scale = 0.07216878364870323f;
    float* C = attn + (((size_t)h) << 20);
#pragma unroll
    for (int mt = 0; mt < 2; mt++) {
        const int row = m0 + wm + mt * 16 + (lane >> 2);
#pragma unroll
        for (int nt = 0; nt < 8; nt++) {
            const int col = n0 + wn + nt * 8 + (lane & 3) * 2;
            *reinterpret_cast<float2*>(C + (size_t)row * S_LEN + col) =
                make_float2(acc[mt][nt][0] * scale, acc[mt][nt][1] * scale);
            *reinterpret_cast<float2*>(C + (size_t)(row + 8) * S_LEN + col) =
                make_float2(acc[mt][nt][2] * scale, acc[mt][nt][3] * scale);
        }
    }
}

// ---------------- AV GEMM (2-pass: split P x single V), ctx -> fp16 ----------
__global__ __launch_bounds__(256, 1) void av_mma(
    const __half* __restrict__ Ph, const __half* __restrict__ Pl,
    const __half* __restrict__ Vth,
    const float* __restrict__ inv_sum, __half* __restrict__ ch)
{
    const int it = blockIdx.y, h = blockIdx.z;
    extern __shared__ __align__(128) char smem[];
    const uint32_t sb = smem_u32(smem);
    const int tid = threadIdx.x;
    const int lane = tid & 31;
    const int wid = tid >> 5;
    const int m0 = it * 128;
    const int wm = (wid & 3) * 32, wn = (wid >> 2) * 64;

    float acc[2][8][4];
#pragma unroll
    for (int mt = 0; mt < 2; mt++)
#pragma unroll
        for (int nt = 0; nt < 8; nt++)
#pragma unroll
            for (int e = 0; e < 4; e++) acc[mt][nt][e] = 0.0f;

    const size_t poff = ((size_t)h) << 20;
    const size_t voff = (size_t)h * DV * S_LEN;
    gemm_body<2>(Ph + poff, Pl + poff, Vth + voff, nullptr,
                 S_LEN, (it + 1) * 2, m0, 0, sb, tid, acc);

#pragma unroll
    for (int mt = 0; mt < 2; mt++)
#pragma unroll
        for (int half_i = 0; half_i < 2; half_i++) {
            const int row = m0 + wm + mt * 16 + (lane >> 2) + half_i * 8;
            const float inv = inv_sum[h * S_LEN + row];
#pragma unroll
            for (int nt = 0; nt < 8; nt++) {
                const int col = wn + nt * 8 + (lane & 3) * 2;
                const size_t o = (size_t)row * CTX_D + (size_t)h * DV + col;
                *reinterpret_cast<__half2*>(ch + o) =
                    __half2(__float2half_rn(acc[mt][nt][half_i * 2] * inv),
                            __float2half_rn(acc[mt][nt][half_i * 2 + 1] * inv));
            }
        }
}

// ---------------- weight converts ----------------
__global__ void conv_w(const float* __restrict__ W, __half* __restrict__ Th, int K, int N)
{
    __shared__ float t[32][33];
    const int k0 = blockIdx.x * 32, n0 = blockIdx.y * 32;
    const int tx = threadIdx.x, ty = threadIdx.y;
#pragma unroll
    for (int i = 0; i < 4; i++) {
        const int k = k0 + ty + i * 8;
        const int n = n0 + tx;
        t[ty + i * 8][tx] = (n < N) ? W[(size_t)k * N + n] : 0.0f;
    }
    __syncthreads();
#pragma unroll
    for (int i = 0; i < 4; i++)
        Th[(size_t)(n0 + ty + i * 8) * K + k0 + tx] = __float2half_rn(t[tx][ty + i * 8]);
}

__global__ void conv_w_split(const float* __restrict__ W, __half* __restrict__ Th,
                             __half* __restrict__ Tl, int K, int N)
{
    __shared__ float t[32][33];
    const int k0 = blockIdx.x * 32, n0 = blockIdx.y * 32;
    const int tx = threadIdx.x, ty = threadIdx.y;
#pragma unroll
    for (int i = 0; i < 4; i++) {
        const int k = k0 + ty + i * 8;
        const int n = n0 + tx;
        t[ty + i * 8][tx] = (n < N) ? W[(size_t)k * N + n] : 0.0f;
    }
    __syncthreads();
#pragma unroll
    for (int i = 0; i < 4; i++) {
        __half h, l;
        split_h(t[tx][ty + i * 8], h, l);
        Th[(size_t)(n0 + ty + i * 8) * K + k0 + tx] = h;
        Tl[(size_t)(n0 + ty + i * 8) * K + k0 + tx] = l;
    }
}

// ---------------- activation convert ----------------
__global__ void conv_a(const float* __restrict__ A, __half* __restrict__ H,
                       __half* __restrict__ L, int n4)
{
    const int i = blockIdx.x * blockDim.x + threadIdx.x;
    if (i >= n4) return;
    const float4 v = reinterpret_cast<const float4*>(A)[i];
    __half h0, l0, h1, l1, h2, l2, h3, l3;
    split_h(v.x, h0, l0); split_h(v.y, h1, l1);
    split_h(v.z, h2, l2); split_h(v.w, h3, l3);
    __half2* Hp = reinterpret_cast<__half2*>(H) + i * 2;
    __half2* Lp = reinterpret_cast<__half2*>(L) + i * 2;
    Hp[0] = __half2(h0, h1); Hp[1] = __half2(h2, h3);
    Lp[0] = __half2(l0, l1); Lp[1] = __half2(l2, l3);
}

// ---------------- rmsnorm fused to fp16 hi/lo ----------------
__global__ void rmsnorm_h(const float* __restrict__ x, const float* __restrict__ gamma,
                          __half* __restrict__ yh, __half* __restrict__ yl,
                          int D, int xstride)
{
    const int row = blockIdx.x;
    const float* xr = x + (size_t)row * xstride;
    float s = 0.0f;
    for (int i = threadIdx.x; i < D; i += 256) { const float v = xr[i]; s += v * v; }
    __shared__ float red[256];
    red[threadIdx.x] = s;
    __syncthreads();
    for (int o = 128; o > 0; o >>= 1) {
        if (threadIdx.x < o) red[threadIdx.x] += red[threadIdx.x + o];
        __syncthreads();
    }
    const float inv = rsqrtf(red[0] / (float)D + 1e-6f);
    for (int i = threadIdx.x; i < D; i += 256) {
        __half h, l;
        split_h(xr[i] * inv * gamma[i], h, l);
        yh[(size_t)row * D + i] = h;
        yl[(size_t)row * D + i] = l;
    }
}

// ---------------- k_pe RoPE ----------------
__global__ void rope_k_kernel(const float* __restrict__ comp, float* __restrict__ kpe)
{
    const int t = blockIdx.x * blockDim.x + threadIdx.x;
    if (t >= S_LEN * 32) return;
    const int d = t & 31;
    const int s = t >> 5;
    float c, sn;
    rope_cs(s, d, c, sn);
    const float* src = comp + (size_t)s * COMP_D + QLORA + KVLORA;
    const float x1 = src[d], x2 = src[d + 32];
    kpe[s * DR + d]      = x1 * c - x2 * sn;
    kpe[s * DR + d + 32] = x2 * c + x1 * sn;
}

// ---------------- broadcast roped k_pe into per-head K cols 128..191 -----------
__global__ void fill_kpe(const float* __restrict__ kpe,
                         __half* __restrict__ Kh, __half* __restrict__ Kl)
{
    const int t = blockIdx.x * blockDim.x + threadIdx.x;
    if (t >= NH * S_LEN * 32) return;
    const int d2 = t & 31;
    const int j  = (t >> 5) & (S_LEN - 1);
    const int h  = t >> 15;
    const int d = d2 * 2;
    __half h0, l0, h1, l1;
    split_h(kpe[j * DR + d], h0, l0);
    split_h(kpe[j * DR + d + 1], h1, l1);
    const size_t o = ((size_t)h * S_LEN + j) * DQK + 128 + d;
    *reinterpret_cast<__half2*>(Kh + o) = __half2(h0, h1);
    *reinterpret_cast<__half2*>(Kl + o) = __half2(l0, l1);
}

// ---------------- build V^T per head (transpose, single fp16) ----------------
__global__ void build_vt(const float* __restrict__ kv, __half* __restrict__ Vth)
{
    __shared__ float t[32][33];
    const int j0 = blockIdx.x * 32, d0 = blockIdx.y * 32, h = blockIdx.z;
    const int tx = threadIdx.x, ty = threadIdx.y;
#pragma unroll
    for (int i = 0; i < 4; i++)
        t[ty + i * 8][tx] = kv[(size_t)(j0 + ty + i * 8) * KVD + h * 256 + 128 + d0 + tx];
    __syncthreads();
    const size_t base = (size_t)h * DV * S_LEN;
#pragma unroll
    for (int i = 0; i < 4; i++)
        Vth[base + (size_t)(d0 + ty + i * 8) * S_LEN + j0 + tx] =
            __float2half_rn(t[tx][ty + i * 8]);
}

// ---------------- softmax: unnormalized exp -> ph/pl fp16, inv_sum ----------------
__global__ void softmax_split(const float* __restrict__ attn,
                              __half* __restrict__ Ph, __half* __restrict__ Pl,
                              float* __restrict__ inv_sum)
{
    const int i = blockIdx.x, h = blockIdx.y;
    const size_t base = (((size_t)h) << 20) + (size_t)i * S_LEN;
    const int len = i + 1;
    const int kend = ((i >> 7) + 1) * 128;
    __shared__ float red[256];

    float m = -3.4e38f;
    for (int j = threadIdx.x; j < len; j += 256) m = fmaxf(m, attn[base + j]);
    red[threadIdx.x] = m;
    __syncthreads();
    for (int o = 128; o > 0; o >>= 1) {
        if (threadIdx.x < o) red[threadIdx.x] = fmaxf(red[threadIdx.x], red[threadIdx.x + o]);
        __syncthreads();
    }
    m = red[0];
    __syncthreads();

    float s = 0.0f;
    for (int j = threadIdx.x; j < len; j += 256) {
        const float p = __expf(attn[base + j] - m);
        s += p;
        __half hh, ll;
        split_h(p, hh, ll);
        Ph[base + j] = hh;
        Pl[base + j] = ll;
    }
    for (int j = len + threadIdx.x; j < kend; j += 256) {
        Ph[base + j] = __float2half_rn(0.0f);
        Pl[base + j] = __float2half_rn(0.0f);
    }
    red[threadIdx.x] = s;
    __syncthreads();
    for (int o = 128; o > 0; o >>= 1) {
        if (threadIdx.x < o) red[threadIdx.x] += red[threadIdx.x + o];
        __syncthreads();
    }
    if (threadIdx.x == 0) inv_sum[h * S_LEN + i] = 1.0f / red[0];
}

// ---------------- launch ----------------
extern "C" void kernel_launch(void* const* d_in, const int* in_sizes, int n_in,
                              void* d_out, int out_size)
{
    const float* hs       = (const float*)d_in[0];
    const float* w_kv_a   = (const float*)d_in[1];
    const float* q_gamma  = (const float*)d_in[2];
    const float* kv_gamma = (const float*)d_in[3];
    const float* w_q_b    = (const float*)d_in[4];
    const float* w_kv_b   = (const float*)d_in[5];
    const float* w_o      = (const float*)d_in[6];
    float* out = (float*)d_out;

    float *comp, *kv, *kpe, *attn, *inv;
    __half *ah, *al, *wah, *wal, *wq, *wkv, *wo, *qh, *ql, *kh, *kl, *vth, *ph, *pl;
    cudaGetSymbolAddress((void**)&comp, g_comp);
    cudaGetSymbolAddress((void**)&ah,   g_ah);
    cudaGetSymbolAddress((void**)&al,   g_al);
    cudaGetSymbolAddress((void**)&wah,  g_wa_h);
    cudaGetSymbolAddress((void**)&wal,  g_wa_l);
    cudaGetSymbolAddress((void**)&wq,   g_wq);
    cudaGetSymbolAddress((void**)&wkv,  g_wkv);
    cudaGetSymbolAddress((void**)&wo,   g_wo);
    cudaGetSymbolAddress((void**)&kv,   g_kv);
    cudaGetSymbolAddress((void**)&kpe,  g_kpe);
    cudaGetSymbolAddress((void**)&attn, g_attn);
    cudaGetSymbolAddress((void**)&qh,   g_qh);
    cudaGetSymbolAddress((void**)&ql,   g_ql);
    cudaGetSymbolAddress((void**)&kh,   g_kh);
    cudaGetSymbolAddress((void**)&kl,   g_kl);
    cudaGetSymbolAddress((void**)&vth,  g_vth);
    cudaGetSymbolAddress((void**)&ph,   g_ph);
    cudaGetSymbolAddress((void**)&pl,   g_pl);
    cudaGetSymbolAddress((void**)&inv,  g_inv);

    cudaFuncSetAttribute(mma_gemm3, cudaFuncAttributeMaxDynamicSharedMemorySize, 131072);
    cudaFuncSetAttribute(mma_gemm_q, cudaFuncAttributeMaxDynamicSharedMemorySize, 98304);
    cudaFuncSetAttribute(mma_gemm_kv, cudaFuncAttributeMaxDynamicSharedMemorySize, 98304);
    cudaFuncSetAttribute(mma_gemm1, cudaFuncAttributeMaxDynamicSharedMemorySize, 65536);
    cudaFuncSetAttribute(score_mma, cudaFuncAttributeMaxDynamicSharedMemorySize, 131072);
    cudaFuncSetAttribute(av_mma, cudaFuncAttributeMaxDynamicSharedMemorySize, 98304);
    const dim3 T256(256);
    const dim3 TW(32, 8);

    // side stream + events (created per call; never destroyed — kernel_launch
    // runs only a handful of times, and destroying during capture is illegal)
    cudaStream_t s2;
    cudaStreamCreateWithFlags(&s2, cudaStreamNonBlocking);
    cudaEvent_t evFork, evA, evQ, evKV, evO;
    cudaEventCreateWithFlags(&evFork, cudaEventDisableTiming);
    cudaEventCreateWithFlags(&evA,    cudaEventDisableTiming);
    cudaEventCreateWithFlags(&evQ,    cudaEventDisableTiming);
    cudaEventCreateWithFlags(&evKV,   cudaEventDisableTiming);
    cudaEventCreateWithFlags(&evO,    cudaEventDisableTiming);

    // fork side stream off the main (legacy) stream
    cudaEventRecord(evFork, 0);
    cudaStreamWaitEvent(s2, evFork, 0);

    // side stream: activation split + independent weight conversions
    conv_a<<<(S_LEN * HID_D / 4 + 255) / 256, 256, 0, s2>>>(hs, ah, al, S_LEN * HID_D / 4);
    cudaEventRecord(evA, s2);
    conv_w<<<dim3(QLORA / 32, QD / 32), TW, 0, s2>>>(w_q_b, wq, QLORA, QD);
    cudaEventRecord(evQ, s2);
    conv_w<<<dim3(KVLORA / 32, KVD / 32), TW, 0, s2>>>(w_kv_b, wkv, KVLORA, KVD);
    cudaEventRecord(evKV, s2);
    conv_w<<<dim3(CTX_D / 32, HID_D / 32), TW, 0, s2>>>(w_o, wo, CTX_D, HID_D);
    cudaEventRecord(evO, s2);

    // main stream
    // 1) comp = hs @ w_kv_a  (3-pass; N pad 2176)
    conv_w_split<<<dim3(HID_D / 32, 2176 / 32), TW>>>(w_kv_a, wah, wal, HID_D, COMP_D);
    cudaStreamWaitEvent(0, evA, 0);
    mma_gemm3<<<dim3(17, 8), T256, 131072>>>(ah, al, wah, wal, comp, COMP_D, HID_D);

    // 2) k_pe RoPE
    rope_k_kernel<<<(S_LEN * 32) / 256, 256>>>(comp, kpe);

    // 3) q = rmsnorm(q_c) @ w_q_b, fused RoPE+split -> per-head Qh/Ql
    rmsnorm_h<<<S_LEN, 256>>>(comp, q_gamma, ah, al, QLORA, COMP_D);
    cudaStreamWaitEvent(0, evQ, 0);
    mma_gemm_q<<<dim3(QD / 128, 8), T256, 98304>>>(ah, al, wq, qh, ql);

    // 4) kv = rmsnorm(kv_c) @ w_kv_b, fused split -> Kh/Kl (nope) + kv fp32 (v)
    rmsnorm_h<<<S_LEN, 256>>>(comp + QLORA, kv_gamma, ah, al, KVLORA, COMP_D);
    cudaStreamWaitEvent(0, evKV, 0);
    mma_gemm_kv<<<dim3(KVD / 128, 8), T256, 98304>>>(ah, al, wkv, kh, kl, kv);
    fill_kpe<<<(NH * S_LEN * 32) / 256, 256>>>(kpe, kh, kl);
    build_vt<<<dim3(32, 4, NH), TW>>>(kv, vth);

    // 5) attention
    score_mma<<<dim3(8, 8, NH), T256, 131072>>>(qh, ql, kh, kl, attn);
    softmax_split<<<dim3(S_LEN, NH), 256>>>(attn, ph, pl, inv);
    av_mma<<<dim3(1, 8, NH), T256, 98304>>>(ph, pl, vth, inv, ah);   // ctx fp16

    // 6) out = ctx @ w_o  (1-pass)
    cudaStreamWaitEvent(0, evO, 0);
    mma_gemm1<<<dim3(HID_D / 128, 8), T256, 65536>>>(ah, wo, out, HID_D, CTX_D);
}

// round 8
// speedup vs baseline: 6.9122x; 1.2156x over previous
#include <cuda_runtime.h>
#include <cuda_fp16.h>
#include <math.h>
#include <stdint.h>

// ---------------- problem constants ----------------
#define S_LEN 1024
#define HID_D 7168
#define NH 128
#define DN 128
#define DR 64
#define DV 128
#define QLORA 1536
#define KVLORA 512
#define COMP_D (QLORA + KVLORA + DR)      // 2112
#define QD (NH * (DN + DR))               // 24576
#define KVD (NH * (DN + DV))              // 32768
#define CTX_D (NH * DV)                   // 16384
#define DQK 192

// ---------------- scratch (device globals) ----------------
__device__ float g_comp[S_LEN * COMP_D];
__device__ __half g_ah[(size_t)S_LEN * 16384];                   // activations hi (also ctx)
__device__ __half g_al[(size_t)S_LEN * 16384];                   // activations lo
__device__ __half g_wa_h[15597568];                              // w_kv_a hi (2176*7168)
__device__ __half g_wa_l[15597568];                              // w_kv_a lo
__device__ __half g_wq[(size_t)QD * QLORA];                      // w_q_b^T
__device__ __half g_wkv[(size_t)KVD * KVLORA];                   // w_kv_b^T
__device__ __half g_wo[(size_t)HID_D * CTX_D];                   // w_o^T
__device__ float g_kv[(size_t)S_LEN * KVD];                      // v half only used
__device__ float g_kpe[S_LEN * DR];
__device__ __half g_qh[(size_t)NH * S_LEN * DQK];
__device__ __half g_ql[(size_t)NH * S_LEN * DQK];
__device__ __half g_kh[(size_t)NH * S_LEN * DQK];
__device__ __half g_kl[(size_t)NH * S_LEN * DQK];
__device__ __half g_vth[(size_t)NH * DV * S_LEN];

// ---------------- PTX helpers ----------------
__device__ __forceinline__ uint32_t smem_u32(const void* p) {
    uint32_t a;
    asm("{ .reg .u64 t; cvta.to.shared.u64 t, %1; cvt.u32.u64 %0, t; }" : "=r"(a) : "l"(p));
    return a;
}
#define CP16(dst, src) \
    asm volatile("cp.async.cg.shared.global [%0], [%1], 16;" :: "r"(dst), "l"(src) : "memory")
#define CP_COMMIT() asm volatile("cp.async.commit_group;" ::: "memory")
#define CP_WAIT1() asm volatile("cp.async.wait_group 1;" ::: "memory")
#define CP_WAIT0() asm volatile("cp.async.wait_group 0;" ::: "memory")

#define LDSM4(r, a) \
    asm volatile("ldmatrix.sync.aligned.m8n8.x4.shared.b16 {%0,%1,%2,%3}, [%4];" \
        : "=r"((r)[0]), "=r"((r)[1]), "=r"((r)[2]), "=r"((r)[3]) : "r"(a))

#define MMA_F16(d, a, b0, b1) \
    asm volatile("mma.sync.aligned.m16n8k16.row.col.f32.f16.f16.f32 " \
        "{%0,%1,%2,%3}, {%4,%5,%6,%7}, {%8,%9}, {%0,%1,%2,%3};" \
        : "+f"((d)[0]), "+f"((d)[1]), "+f"((d)[2]), "+f"((d)[3]) \
        : "r"((a)[0]), "r"((a)[1]), "r"((a)[2]), "r"((a)[3]), "r"(b0), "r"(b1))

#define SWZ(o) ((o) ^ (((o) >> 3) & 0x70))

__device__ __forceinline__ void split_h(float v, __half& h, __half& l) {
    h = __float2half_rn(v);
    l = __float2half_rn(v - __half2float(h));
}

// ---------------- shared GEMM body ----------------
// NPASS=1: ah*bh        NPASS=2: ah*bh + al*bh        NPASS=3: + ah*bl
template <int NPASS>
__device__ __forceinline__ void gemm_body(
    const __half* __restrict__ Ah, const __half* __restrict__ Al,
    const __half* __restrict__ Bh, const __half* __restrict__ Bl,
    int K, int nch, int m0, int n0, uint32_t sb, int tid, float acc[2][8][4])
{
    constexpr int CA = (NPASS >= 2) ? 2 : 1;
    constexpr int CB = (NPASS == 3) ? 2 : 1;
    constexpr int NT = CA + CB;
    constexpr int STAGE = NT * 16384;
    const int lane = tid & 31;
    const int wid = tid >> 5;
    const int wm = (wid & 3) * 32;
    const int wn = (wid >> 2) * 64;

    auto load_stage = [&](int c, int s) {
        const int kc = c << 6;
#pragma unroll
        for (int it = 0; it < NT * 4; it++) {
            const int t = tid + it * 256;
            const int tensor = t >> 10;
            const int rem = t & 1023;
            const int row = rem >> 3;
            const int ch = rem & 7;
            const __half* src;
            int grow;
            if (tensor < CA) {
                src = (CA == 2 && tensor == 1) ? Al : Ah;
                grow = m0 + row;
            } else {
                src = (CB == 2 && tensor == CA + 1) ? Bl : Bh;
                grow = n0 + row;
            }
            const __half* sp = src + (size_t)grow * K + kc + ch * 8;
            const uint32_t dst = sb + s * STAGE + tensor * 16384 + SWZ(row * 128 + ch * 16);
            CP16(dst, sp);
        }
        CP_COMMIT();
    };

    load_stage(0, 0);

    for (int c = 0; c < nch; c++) {
        const int buf = c & 1;
        if (c + 1 < nch) { load_stage(c + 1, buf ^ 1); CP_WAIT1(); }
        else             { CP_WAIT0(); }
        __syncthreads();

        const uint32_t st = sb + buf * STAGE;
        const uint32_t sA_h = st;
        const uint32_t sA_l = st + 16384;
        const uint32_t sB_h = st + CA * 16384;
        const uint32_t sB_l = sB_h + 16384;
        const int rl = lane & 15;
        const int kb = lane >> 4;

#pragma unroll
        for (int k16 = 0; k16 < 4; k16++) {
            const int kbyte = k16 * 32 + kb * 16;
            uint32_t afh[2][4], afl[2][4], bfh[4][4], bfl[4][4];
#pragma unroll
            for (int mt = 0; mt < 2; mt++) {
                const uint32_t off = SWZ((wm + mt * 16 + rl) * 128 + kbyte);
                LDSM4(afh[mt], sA_h + off);
                if (CA == 2) LDSM4(afl[mt], sA_l + off);
            }
#pragma unroll
            for (int q = 0; q < 4; q++) {
                const uint32_t off = SWZ((wn + q * 16 + rl) * 128 + kbyte);
                LDSM4(bfh[q], sB_h + off);
                if (CB == 2) LDSM4(bfl[q], sB_l + off);
            }
#pragma unroll
            for (int mt = 0; mt < 2; mt++)
#pragma unroll
                for (int nt = 0; nt < 8; nt++) {
                    const int q = nt >> 1, s = nt & 1;
                    MMA_F16(acc[mt][nt], afh[mt], bfh[q][s], bfh[q][s + 2]);
                    if (CA == 2) MMA_F16(acc[mt][nt], afl[mt], bfh[q][s], bfh[q][s + 2]);
                    if (CB == 2) MMA_F16(acc[mt][nt], afh[mt], bfl[q][s], bfl[q][s + 2]);
                }
        }
        __syncthreads();
    }
}

#define GEMM_PROLOGUE() \
    extern __shared__ __align__(128) char smem[]; \
    const uint32_t sb = smem_u32(smem); \
    const int tid = threadIdx.x; \
    const int lane = tid & 31; \
    const int wid = tid >> 5; \
    const int m0 = blockIdx.y * 128, n0 = blockIdx.x * 128; \
    const int wm = (wid & 3) * 32, wn = (wid >> 2) * 64; \
    float acc[2][8][4]; \
    _Pragma("unroll") for (int mt = 0; mt < 2; mt++) \
    _Pragma("unroll") for (int nt = 0; nt < 8; nt++) \
    _Pragma("unroll") for (int e = 0; e < 4; e++) acc[mt][nt][e] = 0.0f;

// ---------------- comp GEMM: 3-pass, fp32 out ----------------
__global__ __launch_bounds__(256, 1) void mma_gemm3(
    const __half* __restrict__ Ah, const __half* __restrict__ Al,
    const __half* __restrict__ Bh, const __half* __restrict__ Bl,
    float* __restrict__ C, int N, int K)
{
    GEMM_PROLOGUE();
    gemm_body<3>(Ah, Al, Bh, Bl, K, K >> 6, m0, n0, sb, tid, acc);
#pragma unroll
    for (int mt = 0; mt < 2; mt++) {
        const int row = m0 + wm + mt * 16 + (lane >> 2);
#pragma unroll
        for (int nt = 0; nt < 8; nt++) {
            const int col = n0 + wn + nt * 8 + (lane & 3) * 2;
            if (col < N) {
                *reinterpret_cast<float2*>(C + (size_t)row * N + col) =
                    make_float2(acc[mt][nt][0], acc[mt][nt][1]);
                *reinterpret_cast<float2*>(C + (size_t)(row + 8) * N + col) =
                    make_float2(acc[mt][nt][2], acc[mt][nt][3]);
            }
        }
    }
}

// ---------------- w_o GEMM: 1-pass, fp32 out ----------------
__global__ __launch_bounds__(256, 1) void mma_gemm1(
    const __half* __restrict__ Ah, const __half* __restrict__ Bh,
    float* __restrict__ C, int N, int K)
{
    GEMM_PROLOGUE();
    gemm_body<1>(Ah, nullptr, Bh, nullptr, K, K >> 6, m0, n0, sb, tid, acc);
#pragma unroll
    for (int mt = 0; mt < 2; mt++) {
        const int row = m0 + wm + mt * 16 + (lane >> 2);
#pragma unroll
        for (int nt = 0; nt < 8; nt++) {
            const int col = n0 + wn + nt * 8 + (lane & 3) * 2;
            *reinterpret_cast<float2*>(C + (size_t)row * N + col) =
                make_float2(acc[mt][nt][0], acc[mt][nt][1]);
            *reinterpret_cast<float2*>(C + (size_t)(row + 8) * N + col) =
                make_float2(acc[mt][nt][2], acc[mt][nt][3]);
        }
    }
}

// ---------------- RoPE angle ----------------
__device__ __forceinline__ void rope_cs(int s, int d, float& c, float& sn)
{
    const float inv = exp2f(-(float)d * (13.287712379549449f / 32.0f));
    sincosf((float)s * inv, &sn, &c);
}

// ---------------- q GEMM: 2-pass, fused RoPE + split, per-head layout -----------
__global__ __launch_bounds__(256, 1) void mma_gemm_q(
    const __half* __restrict__ Ah, const __half* __restrict__ Al,
    const __half* __restrict__ Bh,
    __half* __restrict__ Qh, __half* __restrict__ Ql)
{
    GEMM_PROLOGUE();
    gemm_body<2>(Ah, Al, Bh, nullptr, QLORA, QLORA >> 6, m0, n0, sb, tid, acc);

    const int base64 = n0 + wn;
    if ((base64 / 64) % 3 != 2) {
#pragma unroll
        for (int mt = 0; mt < 2; mt++)
#pragma unroll
            for (int half_i = 0; half_i < 2; half_i++) {
                const int row = m0 + wm + mt * 16 + (lane >> 2) + half_i * 8;
#pragma unroll
                for (int nt = 0; nt < 8; nt++) {
                    const int c = base64 + nt * 8 + (lane & 3) * 2;
                    const int h = c / 192;
                    const int cr = c - h * 192;
                    const size_t o = ((size_t)h * S_LEN + row) * DQK + cr;
                    __half h0, l0, h1, l1;
                    split_h(acc[mt][nt][half_i * 2], h0, l0);
                    split_h(acc[mt][nt][half_i * 2 + 1], h1, l1);
                    *reinterpret_cast<__half2*>(Qh + o) = __half2(h0, h1);
                    *reinterpret_cast<__half2*>(Ql + o) = __half2(l0, l1);
                }
            }
    } else {
        const int h = base64 / 192;
#pragma unroll
        for (int mt = 0; mt < 2; mt++)
#pragma unroll
            for (int half_i = 0; half_i < 2; half_i++) {
                const int row = m0 + wm + mt * 16 + (lane >> 2) + half_i * 8;
                const size_t rb = ((size_t)h * S_LEN + row) * DQK + 128;
#pragma unroll
                for (int ntL = 0; ntL < 4; ntL++) {
                    const int d0 = ntL * 8 + (lane & 3) * 2;
                    float o0[2], o1[2];
#pragma unroll
                    for (int e = 0; e < 2; e++) {
                        float cc, ss;
                        rope_cs(row, d0 + e, cc, ss);
                        const float v1 = acc[mt][ntL][half_i * 2 + e];
                        const float v2 = acc[mt][ntL + 4][half_i * 2 + e];
                        o0[e] = v1 * cc - v2 * ss;
                        o1[e] = v2 * cc + v1 * ss;
                    }
                    __half h0, l0, h1, l1;
                    split_h(o0[0], h0, l0); split_h(o0[1], h1, l1);
                    *reinterpret_cast<__half2*>(Qh + rb + d0) = __half2(h0, h1);
                    *reinterpret_cast<__half2*>(Ql + rb + d0) = __half2(l0, l1);
                    split_h(o1[0], h0, l0); split_h(o1[1], h1, l1);
                    *reinterpret_cast<__half2*>(Qh + rb + d0 + 32) = __half2(h0, h1);
                    *reinterpret_cast<__half2*>(Ql + rb + d0 + 32) = __half2(l0, l1);
                }
            }
    }
}

// ---------------- kv GEMM: 2-pass, k_nope -> split per-head; v -> fp32 ----------
__global__ __launch_bounds__(256, 1) void mma_gemm_kv(
    const __half* __restrict__ Ah, const __half* __restrict__ Al,
    const __half* __restrict__ Bh,
    __half* __restrict__ Kh, __half* __restrict__ Kl, float* __restrict__ kv)
{
    GEMM_PROLOGUE();
    gemm_body<2>(Ah, Al, Bh, nullptr, KVLORA, KVLORA >> 6, m0, n0, sb, tid, acc);

    const int base64 = n0 + wn;
    const int blk4 = (base64 / 64) & 3;
    if (blk4 < 2) {
        const int h = base64 / 256;
#pragma unroll
        for (int mt = 0; mt < 2; mt++)
#pragma unroll
            for (int half_i = 0; half_i < 2; half_i++) {
                const int row = m0 + wm + mt * 16 + (lane >> 2) + half_i * 8;
#pragma unroll
                for (int nt = 0; nt < 8; nt++) {
                    const int c = base64 + nt * 8 + (lane & 3) * 2;
                    const int cr = c - h * 256;
                    const size_t o = ((size_t)h * S_LEN + row) * DQK + cr;
                    __half h0, l0, h1, l1;
                    split_h(acc[mt][nt][half_i * 2], h0, l0);
                    split_h(acc[mt][nt][half_i * 2 + 1], h1, l1);
                    *reinterpret_cast<__half2*>(Kh + o) = __half2(h0, h1);
                    *reinterpret_cast<__half2*>(Kl + o) = __half2(l0, l1);
                }
            }
    } else {
#pragma unroll
        for (int mt = 0; mt < 2; mt++) {
            const int row = m0 + wm + mt * 16 + (lane >> 2);
#pragma unroll
            for (int nt = 0; nt < 8; nt++) {
                const int c = base64 + nt * 8 + (lane & 3) * 2;
                *reinterpret_cast<float2*>(kv + (size_t)row * KVD + c) =
                    make_float2(acc[mt][nt][0], acc[mt][nt][1]);
                *reinterpret_cast<float2*>(kv + (size_t)(row + 8) * KVD + c) =
                    make_float2(acc[mt][nt][2], acc[mt][nt][3]);
            }
        }
    }
}

// ---------------- fused flash attention per (head, i-tile) ----------------
// smem: [0,128K) gemm stages (reused for P after S phase), [128K,160K) V tile
__global__ __launch_bounds__(256, 1) void flash_mma(
    const __half* __restrict__ Qh, const __half* __restrict__ Ql,
    const __half* __restrict__ Kh, const __half* __restrict__ Kl,
    const __half* __restrict__ Vth, __half* __restrict__ ch)
{
    extern __shared__ __align__(128) char smem[];
    __shared__ float redM[2][128];
    __shared__ float redS[2][128];
    const uint32_t sb = smem_u32(smem);
    const int tid = threadIdx.x;
    const int lane = tid & 31;
    const int wid = tid >> 5;
    const int h = blockIdx.x;
    const int it = 7 - blockIdx.y;          // heavy tiles first
    const int m0 = it * 128;
    const int wm = (wid & 3) * 32, wn = (wid >> 2) * 64;
    const int ng = wid >> 2;
    const size_t hoff = (size_t)h * S_LEN * DQK;
    const size_t voff = (size_t)h * DV * S_LEN;
    const float scale = 0.07216878364870323f;   // 1/sqrt(192)

    float Oacc[2][8][4];
    float mrow[2][2], lrow[2][2];
#pragma unroll
    for (int mt = 0; mt < 2; mt++)
#pragma unroll
        for (int nt = 0; nt < 8; nt++)
#pragma unroll
            for (int e = 0; e < 4; e++) Oacc[mt][nt][e] = 0.0f;
#pragma unroll
    for (int mt = 0; mt < 2; mt++)
#pragma unroll
        for (int hf = 0; hf < 2; hf++) { mrow[mt][hf] = -3.4e38f; lrow[mt][hf] = 0.0f; }

    for (int jt = 0; jt <= it; jt++) {
        // ---- S = Q @ K^T (3-pass split) ----
        float Sacc[2][8][4];
#pragma unroll
        for (int mt = 0; mt < 2; mt++)
#pragma unroll
            for (int nt = 0; nt < 8; nt++)
#pragma unroll
                for (int e = 0; e < 4; e++) Sacc[mt][nt][e] = 0.0f;

        gemm_body<3>(Qh + hoff, Ql + hoff, Kh + hoff, Kl + hoff,
                     DQK, 3, m0, jt * 128, sb, tid, Sacc);

        // ---- prefetch V tile (2 chunks of [128 d][64 j]) ----
#pragma unroll
        for (int itv = 0; itv < 8; itv++) {
            const int t = tid + itv * 256;
            const int c = t >> 10;
            const int rem = t & 1023;
            const int d = rem >> 3;
            const int seg = rem & 7;
            const __half* sp = Vth + voff + (size_t)d * S_LEN + jt * 128 + c * 64 + seg * 8;
            CP16(sb + 131072 + c * 16384 + SWZ(d * 128 + seg * 16), sp);
        }
        CP_COMMIT();

        // ---- pass A: scale + mask + row max ----
#pragma unroll
        for (int mt = 0; mt < 2; mt++)
#pragma unroll
            for (int hf = 0; hf < 2; hf++) {
                const int rloc = wm + mt * 16 + (lane >> 2) + hf * 8;
                float mx = -3.4e38f;
#pragma unroll
                for (int nt = 0; nt < 8; nt++)
#pragma unroll
                    for (int e = 0; e < 2; e++) {
                        float s = Sacc[mt][nt][hf * 2 + e] * scale;
                        if (jt == it) {
                            const int cg = jt * 128 + wn + nt * 8 + (lane & 3) * 2 + e;
                            if (cg > m0 + rloc) s = -3.4e38f;
                        }
                        Sacc[mt][nt][hf * 2 + e] = s;
                        mx = fmaxf(mx, s);
                    }
                mx = fmaxf(mx, __shfl_xor_sync(0xFFFFFFFFu, mx, 1));
                mx = fmaxf(mx, __shfl_xor_sync(0xFFFFFFFFu, mx, 2));
                if ((lane & 3) == 0) redM[ng][rloc] = mx;
            }
        __syncthreads();

        // ---- pass B: exp, write P (hi/lo) to smem, partial row sums, O rescale ----
#pragma unroll
        for (int mt = 0; mt < 2; mt++)
#pragma unroll
            for (int hf = 0; hf < 2; hf++) {
                const int rloc = wm + mt * 16 + (lane >> 2) + hf * 8;
                const float mnew = fmaxf(mrow[mt][hf],
                                         fmaxf(redM[0][rloc], redM[1][rloc]));
                float ssum = 0.0f;
#pragma unroll
                for (int nt = 0; nt < 8; nt++) {
                    const float p0 = __expf(Sacc[mt][nt][hf * 2] - mnew);
                    const float p1 = __expf(Sacc[mt][nt][hf * 2 + 1] - mnew);
                    ssum += p0 + p1;
                    __half h0, l0, h1, l1;
                    split_h(p0, h0, l0);
                    split_h(p1, h1, l1);
                    const uint32_t off = SWZ(rloc * 128 + (nt * 8 + (lane & 3) * 2) * 2);
                    *reinterpret_cast<__half2*>(smem + ng * 16384 + off) = __half2(h0, h1);
                    *reinterpret_cast<__half2*>(smem + 32768 + ng * 16384 + off) = __half2(l0, l1);
                }
                ssum += __shfl_xor_sync(0xFFFFFFFFu, ssum, 1);
                ssum += __shfl_xor_sync(0xFFFFFFFFu, ssum, 2);
                if ((lane & 3) == 0) redS[ng][rloc] = ssum;
                const float sc = __expf(mrow[mt][hf] - mnew);
#pragma unroll
                for (int nt = 0; nt < 8; nt++) {
                    Oacc[mt][nt][hf * 2] *= sc;
                    Oacc[mt][nt][hf * 2 + 1] *= sc;
                }
                lrow[mt][hf] *= sc;
                mrow[mt][hf] = mnew;
            }
        __syncthreads();

        // ---- pass C: finish l ----
#pragma unroll
        for (int mt = 0; mt < 2; mt++)
#pragma unroll
            for (int hf = 0; hf < 2; hf++) {
                const int rloc = wm + mt * 16 + (lane >> 2) + hf * 8;
                lrow[mt][hf] += redS[0][rloc] + redS[1][rloc];
            }

        // ---- P @ V (2-pass: Ph, Pl), accumulate into Oacc ----
        CP_WAIT0();
        __syncthreads();
        const int rl = lane & 15;
        const int kb = lane >> 4;
#pragma unroll
        for (int c = 0; c < 2; c++) {
#pragma unroll
            for (int k16 = 0; k16 < 4; k16++) {
                const int kbyte = k16 * 32 + kb * 16;
                uint32_t pfh[2][4], pfl[2][4], vf[4][4];
#pragma unroll
                for (int mt = 0; mt < 2; mt++) {
                    const uint32_t off = SWZ((wm + mt * 16 + rl) * 128 + kbyte);
                    LDSM4(pfh[mt], sb + c * 16384 + off);
                    LDSM4(pfl[mt], sb + 32768 + c * 16384 + off);
                }
#pragma unroll
                for (int q = 0; q < 4; q++) {
                    const uint32_t off = SWZ((wn + q * 16 + rl) * 128 + kbyte);
                    LDSM4(vf[q], sb + 131072 + c * 16384 + off);
                }
#pragma unroll
                for (int mt = 0; mt < 2; mt++)
#pragma unroll
                    for (int nt = 0; nt < 8; nt++) {
                        const int q = nt >> 1, s = nt & 1;
                        MMA_F16(Oacc[mt][nt], pfh[mt], vf[q][s], vf[q][s + 2]);
                        MMA_F16(Oacc[mt][nt], pfl[mt], vf[q][s], vf[q][s + 2]);
                    }
            }
        }
        __syncthreads();   // protect P/V smem before next jt's loads
    }

    // ---- epilogue: normalize and write ctx fp16 ----
#pragma unroll
    for (int mt = 0; mt < 2; mt++)
#pragma unroll
        for (int hf = 0; hf < 2; hf++) {
            const int row = m0 + wm + mt * 16 + (lane >> 2) + hf * 8;
            const float inv = 1.0f / lrow[mt][hf];
#pragma unroll
            for (int nt = 0; nt < 8; nt++) {
                const int col = wn + nt * 8 + (lane & 3) * 2;
                const size_t o = (size_t)row * CTX_D + (size_t)h * DV + col;
                *reinterpret_cast<__half2*>(ch + o) =
                    __half2(__float2half_rn(Oacc[mt][nt][hf * 2] * inv),
                            __float2half_rn(Oacc[mt][nt][hf * 2 + 1] * inv));
            }
        }
}

// ---------------- weight converts ----------------
// vectorized: 64k x 32n tile, __half2 stores
__global__ void conv_w2(const float* __restrict__ W, __half* __restrict__ Th, int K, int N)
{
    __shared__ float t[64][33];
    const int k0 = blockIdx.x * 64, n0 = blockIdx.y * 32;
    const int tx = threadIdx.x, ty = threadIdx.y;
#pragma unroll
    for (int i = 0; i < 8; i++)
        t[ty + i * 8][tx] = W[(size_t)(k0 + ty + i * 8) * N + n0 + tx];
    __syncthreads();
#pragma unroll
    for (int i = 0; i < 4; i++) {
        const int n = n0 + ty + i * 8;
        const int cidx = ty + i * 8;
        __half2 v = __half2(__float2half_rn(t[tx * 2][cidx]),
                            __float2half_rn(t[tx * 2 + 1][cidx]));
        *reinterpret_cast<__half2*>(Th + (size_t)n * K + k0 + tx * 2) = v;
    }
}

__global__ void conv_w_split(const float* __restrict__ W, __half* __restrict__ Th,
                             __half* __restrict__ Tl, int K, int N)
{
    __shared__ float t[32][33];
    const int k0 = blockIdx.x * 32, n0 = blockIdx.y * 32;
    const int tx = threadIdx.x, ty = threadIdx.y;
#pragma unroll
    for (int i = 0; i < 4; i++) {
        const int k = k0 + ty + i * 8;
        const int n = n0 + tx;
        t[ty + i * 8][tx] = (n < N) ? W[(size_t)k * N + n] : 0.0f;
    }
    __syncthreads();
#pragma unroll
    for (int i = 0; i < 4; i++) {
        __half h, l;
        split_h(t[tx][ty + i * 8], h, l);
        Th[(size_t)(n0 + ty + i * 8) * K + k0 + tx] = h;
        Tl[(size_t)(n0 + ty + i * 8) * K + k0 + tx] = l;
    }
}

// ---------------- activation convert ----------------
__global__ void conv_a(const float* __restrict__ A, __half* __restrict__ H,
                       __half* __restrict__ L, int n4)
{
    const int i = blockIdx.x * blockDim.x + threadIdx.x;
    if (i >= n4) return;
    const float4 v = reinterpret_cast<const float4*>(A)[i];
    __half h0, l0, h1, l1, h2, l2, h3, l3;
    split_h(v.x, h0, l0); split_h(v.y, h1, l1);
    split_h(v.z, h2, l2); split_h(v.w, h3, l3);
    __half2* Hp = reinterpret_cast<__half2*>(H) + i * 2;
    __half2* Lp = reinterpret_cast<__half2*>(L) + i * 2;
    Hp[0] = __half2(h0, h1); Hp[1] = __half2(h2, h3);
    Lp[0] = __half2(l0, l1); Lp[1] = __half2(l2, l3);
}

// ---------------- rmsnorm fused to fp16 hi/lo ----------------
__global__ void rmsnorm_h(const float* __restrict__ x, const float* __restrict__ gamma,
                          __half* __restrict__ yh, __half* __restrict__ yl,
                          int D, int xstride)
{
    const int row = blockIdx.x;
    const float* xr = x + (size_t)row * xstride;
    float s = 0.0f;
    for (int i = threadIdx.x; i < D; i += 256) { const float v = xr[i]; s += v * v; }
    __shared__ float red[256];
    red[threadIdx.x] = s;
    __syncthreads();
    for (int o = 128; o > 0; o >>= 1) {
        if (threadIdx.x < o) red[threadIdx.x] += red[threadIdx.x + o];
        __syncthreads();
    }
    const float inv = rsqrtf(red[0] / (float)D + 1e-6f);
    for (int i = threadIdx.x; i < D; i += 256) {
        __half h, l;
        split_h(xr[i] * inv * gamma[i], h, l);
        yh[(size_t)row * D + i] = h;
        yl[(size_t)row * D + i] = l;
    }
}

// ---------------- k_pe RoPE ----------------
__global__ void rope_k_kernel(const float* __restrict__ comp, float* __restrict__ kpe)
{
    const int t = blockIdx.x * blockDim.x + threadIdx.x;
    if (t >= S_LEN * 32) return;
    const int d = t & 31;
    const int s = t >> 5;
    float c, sn;
    rope_cs(s, d, c, sn);
    const float* src = comp + (size_t)s * COMP_D + QLORA + KVLORA;
    const float x1 = src[d], x2 = src[d + 32];
    kpe[s * DR + d]      = x1 * c - x2 * sn;
    kpe[s * DR + d + 32] = x2 * c + x1 * sn;
}

// ---------------- broadcast roped k_pe into per-head K cols 128..191 -----------
__global__ void fill_kpe(const float* __restrict__ kpe,
                         __half* __restrict__ Kh, __half* __restrict__ Kl)
{
    const int t = blockIdx.x * blockDim.x + threadIdx.x;
    if (t >= NH * S_LEN * 32) return;
    const int d2 = t & 31;
    const int j  = (t >> 5) & (S_LEN - 1);
    const int h  = t >> 15;
    const int d = d2 * 2;
    __half h0, l0, h1, l1;
    split_h(kpe[j * DR + d], h0, l0);
    split_h(kpe[j * DR + d + 1], h1, l1);
    const size_t o = ((size_t)h * S_LEN + j) * DQK + 128 + d;
    *reinterpret_cast<__half2*>(Kh + o) = __half2(h0, h1);
    *reinterpret_cast<__half2*>(Kl + o) = __half2(l0, l1);
}

// ---------------- build V^T per head (transpose, single fp16) ----------------
__global__ void build_vt(const float* __restrict__ kv, __half* __restrict__ Vth)
{
    __shared__ float t[32][33];
    const int j0 = blockIdx.x * 32, d0 = blockIdx.y * 32, h = blockIdx.z;
    const int tx = threadIdx.x, ty = threadIdx.y;
#pragma unroll
    for (int i = 0; i < 4; i++)
        t[ty + i * 8][tx] = kv[(size_t)(j0 + ty + i * 8) * KVD + h * 256 + 128 + d0 + tx];
    __syncthreads();
    const size_t base = (size_t)h * DV * S_LEN;
#pragma unroll
    for (int i = 0; i < 4; i++)
        Vth[base + (size_t)(d0 + ty + i * 8) * S_LEN + j0 + tx] =
            __float2half_rn(t[tx][ty + i * 8]);
}

// ---------------- launch ----------------
extern "C" void kernel_launch(void* const* d_in, const int* in_sizes, int n_in,
                              void* d_out, int out_size)
{
    const float* hs       = (const float*)d_in[0];
    const float* w_kv_a   = (const float*)d_in[1];
    const float* q_gamma  = (const float*)d_in[2];
    const float* kv_gamma = (const float*)d_in[3];
    const float* w_q_b    = (const float*)d_in[4];
    const float* w_kv_b   = (const float*)d_in[5];
    const float* w_o      = (const float*)d_in[6];
    float* out = (float*)d_out;

    float *comp, *kv, *kpe;
    __half *ah, *al, *wah, *wal, *wq, *wkv, *wo, *qh, *ql, *kh, *kl, *vth;
    cudaGetSymbolAddress((void**)&comp, g_comp);
    cudaGetSymbolAddress((void**)&ah,   g_ah);
    cudaGetSymbolAddress((void**)&al,   g_al);
    cudaGetSymbolAddress((void**)&wah,  g_wa_h);
    cudaGetSymbolAddress((void**)&wal,  g_wa_l);
    cudaGetSymbolAddress((void**)&wq,   g_wq);
    cudaGetSymbolAddress((void**)&wkv,  g_wkv);
    cudaGetSymbolAddress((void**)&wo,   g_wo);
    cudaGetSymbolAddress((void**)&kv,   g_kv);
    cudaGetSymbolAddress((void**)&kpe,  g_kpe);
    cudaGetSymbolAddress((void**)&qh,   g_qh);
    cudaGetSymbolAddress((void**)&ql,   g_ql);
    cudaGetSymbolAddress((void**)&kh,   g_kh);
    cudaGetSymbolAddress((void**)&kl,   g_kl);
    cudaGetSymbolAddress((void**)&vth,  g_vth);

    cudaFuncSetAttribute(mma_gemm3, cudaFuncAttributeMaxDynamicSharedMemorySize, 131072);
    cudaFuncSetAttribute(mma_gemm_q, cudaFuncAttributeMaxDynamicSharedMemorySize, 98304);
    cudaFuncSetAttribute(mma_gemm_kv, cudaFuncAttributeMaxDynamicSharedMemorySize, 98304);
    cudaFuncSetAttribute(mma_gemm1, cudaFuncAttributeMaxDynamicSharedMemorySize, 65536);
    cudaFuncSetAttribute(flash_mma, cudaFuncAttributeMaxDynamicSharedMemorySize, 163840);
    const dim3 T256(256);
    const dim3 TW(32, 8);

    // side stream + events (created per call; never destroyed)
    cudaStream_t s2;
    cudaStreamCreateWithFlags(&s2, cudaStreamNonBlocking);
    cudaEvent_t evFork, evA, evQ, evKV, evO;
    cudaEventCreateWithFlags(&evFork, cudaEventDisableTiming);
    cudaEventCreateWithFlags(&evA,    cudaEventDisableTiming);
    cudaEventCreateWithFlags(&evQ,    cudaEventDisableTiming);
    cudaEventCreateWithFlags(&evKV,   cudaEventDisableTiming);
    cudaEventCreateWithFlags(&evO,    cudaEventDisableTiming);

    cudaEventRecord(evFork, 0);
    cudaStreamWaitEvent(s2, evFork, 0);

    // side stream: activation split + independent weight conversions
    conv_a<<<(S_LEN * HID_D / 4 + 255) / 256, 256, 0, s2>>>(hs, ah, al, S_LEN * HID_D / 4);
    cudaEventRecord(evA, s2);
    conv_w2<<<dim3(QLORA / 64, QD / 32), TW, 0, s2>>>(w_q_b, wq, QLORA, QD);
    cudaEventRecord(evQ, s2);
    conv_w2<<<dim3(KVLORA / 64, KVD / 32), TW, 0, s2>>>(w_kv_b, wkv, KVLORA, KVD);
    cudaEventRecord(evKV, s2);
    conv_w2<<<dim3(CTX_D / 64, HID_D / 32), TW, 0, s2>>>(w_o, wo, CTX_D, HID_D);
    cudaEventRecord(evO, s2);

    // main stream
    // 1) comp = hs @ w_kv_a  (3-pass; N pad 2176)
    conv_w_split<<<dim3(HID_D / 32, 2176 / 32), TW>>>(w_kv_a, wah, wal, HID_D, COMP_D);
    cudaStreamWaitEvent(0, evA, 0);
    mma_gemm3<<<dim3(17, 8), T256, 131072>>>(ah, al, wah, wal, comp, COMP_D, HID_D);

    // 2) k_pe RoPE
    rope_k_kernel<<<(S_LEN * 32) / 256, 256>>>(comp, kpe);

    // 3) q = rmsnorm(q_c) @ w_q_b, fused RoPE+split -> per-head Qh/Ql
    rmsnorm_h<<<S_LEN, 256>>>(comp, q_gamma, ah, al, QLORA, COMP_D);
    cudaStreamWaitEvent(0, evQ, 0);
    mma_gemm_q<<<dim3(QD / 128, 8), T256, 98304>>>(ah, al, wq, qh, ql);

    // 4) kv = rmsnorm(kv_c) @ w_kv_b, fused split -> Kh/Kl (nope) + kv fp32 (v)
    rmsnorm_h<<<S_LEN, 256>>>(comp + QLORA, kv_gamma, ah, al, KVLORA, COMP_D);
    cudaStreamWaitEvent(0, evKV, 0);
    mma_gemm_kv<<<dim3(KVD / 128, 8), T256, 98304>>>(ah, al, wkv, kh, kl, kv);
    fill_kpe<<<(NH * S_LEN * 32) / 256, 256>>>(kpe, kh, kl);
    build_vt<<<dim3(32, 4, NH), TW>>>(kv, vth);

    // 5) fused flash attention -> ctx fp16 in ah
    flash_mma<<<dim3(NH, 8), T256, 163840>>>(qh, ql, kh, kl, vth, ah);

    // 6) out = ctx @ w_o  (1-pass)
    cudaStreamWaitEvent(0, evO, 0);
    mma_gemm1<<<dim3(HID_D / 128, 8), T256, 65536>>>(ah, wo, out, HID_D, CTX_D);
}